// round 14
// baseline (speedup 1.0000x reference)
#include <cuda_runtime.h>
#include <cuda_bf16.h>
#include <cuda_fp16.h>
#include <math.h>
#include <stdint.h>

#define BB 16
#define NN 1024
#define DD 128
#define HH 8
#define NUMN 8
#define NUMJ 4
#define ROWS (BB*NN)   /* 16384 */

// ---------------- scratch (device globals; no allocation) ----------------
__device__ float g_eig[ROWS*DD];          // fp32 residual stream
__device__ float g_part[BB*8*DD];         // pooled partial sums
__device__ float g_coe[BB*20];
__device__ float g_qkvbias[3*DD];         // q-part pre-scaled
__device__ uint4 g_h1[ROWS*DD/8];         // bf16 LN1 output
__device__ uint4 g_qkv4[ROWS*3*DD/8];     // q|k bf16, v f16 (q pre-scaled)
__device__ uint4 g_att4[ROWS*DD/8];       // bf16 attention output
__device__ uint4 g_h2[ROWS*DD/8];         // bf16 LN2 output
__device__ uint4 g_f14[ROWS*DD/8];        // bf16 ffn intermediate
__device__ uint4 g_wqkv4[3*DD*DD/8];      // bf16 weights
__device__ uint4 g_wout4[DD*DD/8];
__device__ uint4 g_wf14[DD*DD/8];
__device__ uint4 g_wf24[DD*DD/8];

#define QSCALE (0.25f * 1.4426950408889634f)   /* 1/sqrt(dh) * log2(e) */

__device__ __forceinline__ uint32_t packbf(float lo, float hi) {
    __nv_bfloat162 v = __floats2bfloat162_rn(lo, hi);
    return *reinterpret_cast<uint32_t*>(&v);
}
__device__ __forceinline__ void mma_bf16(float c[4],
                                         uint32_t a0, uint32_t a1, uint32_t a2, uint32_t a3,
                                         uint32_t b0, uint32_t b1) {
    asm("mma.sync.aligned.m16n8k16.row.col.f32.bf16.bf16.f32 "
        "{%0,%1,%2,%3},{%4,%5,%6,%7},{%8,%9},{%0,%1,%2,%3};"
        : "+f"(c[0]), "+f"(c[1]), "+f"(c[2]), "+f"(c[3])
        : "r"(a0), "r"(a1), "r"(a2), "r"(a3), "r"(b0), "r"(b1));
}
__device__ __forceinline__ void mma_f16(float c[4],
                                        uint32_t a0, uint32_t a1, uint32_t a2, uint32_t a3,
                                        uint32_t b0, uint32_t b1) {
    asm("mma.sync.aligned.m16n8k16.row.col.f32.f16.f16.f32 "
        "{%0,%1,%2,%3},{%4,%5,%6,%7},{%8,%9},{%0,%1,%2,%3};"
        : "+f"(c[0]), "+f"(c[1]), "+f"(c[2]), "+f"(c[3])
        : "r"(a0), "r"(a1), "r"(a2), "r"(a3), "r"(b0), "r"(b1));
}
__device__ __forceinline__ uint32_t exp2h2(float lo, float hi) {
    __half2 h = h2exp2(__floats2half2_rn(lo, hi));   // 1 MUFU per 2 values
    return *reinterpret_cast<uint32_t*>(&h);
}
__device__ __forceinline__ uint32_t packh(float lo, float hi) {
    __half2 h = __floats2half2_rn(lo, hi);
    return *reinterpret_cast<uint32_t*>(&h);
}

// ---------------- 0) one-time weight conversion to bf16 ----------------
__global__ void wconv_kernel(const float* __restrict__ qkvW, const float* __restrict__ qkvB,
                             const float* __restrict__ outW, const float* __restrict__ f1W,
                             const float* __restrict__ f2W) {
    const int stride = gridDim.x * blockDim.x;
    const int i0 = blockIdx.x * blockDim.x + threadIdx.x;
    __nv_bfloat16* wq = (__nv_bfloat16*)g_wqkv4;
    __nv_bfloat16* wo = (__nv_bfloat16*)g_wout4;
    __nv_bfloat16* w1 = (__nv_bfloat16*)g_wf14;
    __nv_bfloat16* w2 = (__nv_bfloat16*)g_wf24;
    for (int i = i0; i < 3*DD*DD; i += stride) {
        float v = qkvW[i];
        if (i < DD*DD) v *= QSCALE;           // fold Q scale into Wq
        wq[i] = __float2bfloat16(v);
    }
    for (int i = i0; i < DD*DD; i += stride) {
        wo[i] = __float2bfloat16(outW[i]);
        w1[i] = __float2bfloat16(f1W[i]);
        w2[i] = __float2bfloat16(f2W[i]);
    }
    if (i0 < 3*DD) g_qkvbias[i0] = qkvB[i0] * (i0 < DD ? QSCALE : 1.0f);
}

// ---------------- 1) sine encoding + projection + fused LN1 (4 rows/iter) ----------------
__global__ void encode_kernel(const float* __restrict__ eva,
                              const float* __restrict__ W,
                              const float* __restrict__ bias,
                              const float* __restrict__ lns,
                              const float* __restrict__ lnb) {
    extern __shared__ float sm[];
    float* Wsh  = sm;            // [128][132]
    float* eeig = sm + 128*132;  // [4][132]
    __shared__ float red1[4][4];
    __shared__ float red2[4][4];
    const int t = threadIdx.x;   // 128
    const int wid = t >> 5, lane = t & 31;

    for (int idx = t; idx < 128*129; idx += 128) {
        int d = idx / 129, i = idx % 129;
        Wsh[d*132 + i] = W[idx];
    }
    const float bs = bias[t];
    const float s1 = lns[t], b1 = lnb[t];
    const int f = t & 63, rr = t >> 6;
    const float divt = expf(-(float)(2*f) * (9.210340371976184f / 128.0f));
    const int row0 = blockIdx.x * 64;
    uint32_t* h1 = (uint32_t*)g_h1;
    __syncthreads();

    for (int r4 = 0; r4 < 64; r4 += 4) {
        #pragma unroll
        for (int j = 0; j < 2; ++j) {
            const int r = rr + 2*j;
            const float e = eva[row0 + r4 + r];
            float pe = e * 100.0f * divt;
            float s, c;
            sincosf(pe, &s, &c);
            eeig[r*132 + 1 + f]  = s;
            eeig[r*132 + 65 + f] = c;
            if (f == 0) eeig[r*132] = e;
        }
        __syncthreads();

        float acc[4] = {bs, bs, bs, bs};
        const float4* Wv = (const float4*)(Wsh + t*132);
        const float4* E0 = (const float4*)(eeig);
        const float4* E1 = (const float4*)(eeig + 132);
        const float4* E2 = (const float4*)(eeig + 264);
        const float4* E3 = (const float4*)(eeig + 396);
        #pragma unroll 4
        for (int i4 = 0; i4 < 32; ++i4) {
            float4 w = Wv[i4];
            float4 e0 = E0[i4], e1 = E1[i4], e2 = E2[i4], e3 = E3[i4];
            acc[0] += w.x*e0.x + w.y*e0.y + w.z*e0.z + w.w*e0.w;
            acc[1] += w.x*e1.x + w.y*e1.y + w.z*e1.z + w.w*e1.w;
            acc[2] += w.x*e2.x + w.y*e2.y + w.z*e2.z + w.w*e2.w;
            acc[3] += w.x*e3.x + w.y*e3.y + w.z*e3.z + w.w*e3.w;
        }
        const float wlast = Wsh[t*132 + 128];
        #pragma unroll
        for (int r = 0; r < 4; ++r) acc[r] += wlast * eeig[r*132 + 128];

        // store fp32 + LN over 4 rows
        #pragma unroll
        for (int r = 0; r < 4; ++r) {
            g_eig[(size_t)(row0 + r4 + r)*DD + t] = acc[r];
            float x = acc[r];
            #pragma unroll
            for (int o = 16; o; o >>= 1) x += __shfl_xor_sync(0xffffffffu, x, o);
            if (lane == 0) red1[r][wid] = x;
        }
        __syncthreads();
        float dd[4];
        #pragma unroll
        for (int r = 0; r < 4; ++r) {
            const float mean = (red1[r][0]+red1[r][1]+red1[r][2]+red1[r][3]) * (1.0f/128.0f);
            dd[r] = acc[r] - mean;
            float q = dd[r] * dd[r];
            #pragma unroll
            for (int o = 16; o; o >>= 1) q += __shfl_xor_sync(0xffffffffu, q, o);
            if (lane == 0) red2[r][wid] = q;
        }
        __syncthreads();
        #pragma unroll
        for (int r = 0; r < 4; ++r) {
            const float var = (red2[r][0]+red2[r][1]+red2[r][2]+red2[r][3]) * (1.0f/128.0f);
            const float h = dd[r] * rsqrtf(var + 1e-5f) * s1 + b1;
            const float hh = __shfl_down_sync(0xffffffffu, h, 1);
            if (!(t & 1)) h1[(row0 + r4 + r)*64 + (t >> 1)] = packbf(h, hh);
        }
        __syncthreads();
    }
}

// ---------------- 2) bf16 GEMM, copy-only staging ----------------
// EPI 0: bf16 out; 1: gelu + bf16 out; 2: residual + fp32 out;
// EPI 3: qkv -> bf16 out for q|k columns, f16 out for v columns (n0 >= 256)
template <int EPI>
__global__ void __launch_bounds__(128) gemm_bb(const __nv_bfloat16* __restrict__ A,
                                               const __nv_bfloat16* __restrict__ W,
                                               const float* __restrict__ bias,
                                               const float* __restrict__ res,
                                               uint32_t* __restrict__ Cb,
                                               float* __restrict__ Cf,
                                               int Nout) {
    __shared__ __align__(16) uint32_t As[64*68];
    __shared__ __align__(16) uint32_t Ws[64*68];
    const int tid  = threadIdx.x;          // 128
    const int m0   = blockIdx.y * 64;
    const int n0   = blockIdx.x * 64;
    const int warp = tid >> 5, lane = tid & 31;
    const int g = lane >> 2, t = lane & 3;
    const int wm = (warp >> 1) * 32, wn = (warp & 1) * 32;

    {
        const int r = tid >> 1, j0 = (tid & 1) * 8;
        const uint4* Ag = (const uint4*)(A + (size_t)(m0 + r) * 128) + j0;
        const uint4* Wg = (const uint4*)(W + (size_t)(n0 + r) * 128) + j0;
        uint4* Ad = (uint4*)(As + r*68) + j0;
        uint4* Wd = (uint4*)(Ws + r*68) + j0;
        #pragma unroll
        for (int j = 0; j < 8; ++j) { Ad[j] = Ag[j]; Wd[j] = Wg[j]; }
    }
    __syncthreads();

    float acc[2][4][4] = {};
    #pragma unroll
    for (int k = 0; k < 8; ++k) {
        const int k0 = k * 8;
        uint32_t af[2][4];
        #pragma unroll
        for (int mg = 0; mg < 2; ++mg) {
            const uint32_t* ap = As + (wm + mg*16 + g) * 68 + k0;
            af[mg][0] = ap[t];
            af[mg][1] = ap[8*68 + t];
            af[mg][2] = ap[t + 4];
            af[mg][3] = ap[8*68 + t + 4];
        }
        #pragma unroll
        for (int ng = 0; ng < 4; ++ng) {
            const uint32_t* wp = Ws + (wn + ng*8 + g) * 68 + k0;
            const uint32_t b0 = wp[t];
            const uint32_t b1 = wp[t + 4];
            mma_bf16(acc[0][ng], af[0][0], af[0][1], af[0][2], af[0][3], b0, b1);
            mma_bf16(acc[1][ng], af[1][0], af[1][1], af[1][2], af[1][3], b0, b1);
        }
    }

    const bool vf16 = (EPI == 3) && (n0 >= 256);   // V block -> f16 packing
    #pragma unroll
    for (int mg = 0; mg < 2; ++mg) {
        const int row0 = m0 + wm + mg*16 + g;
        const int row1 = row0 + 8;
        #pragma unroll
        for (int ng = 0; ng < 4; ++ng) {
            const int col = n0 + wn + ng*8 + 2*t;
            float2 b2 = *(const float2*)&bias[col];
            float2 v0 = make_float2(acc[mg][ng][0] + b2.x, acc[mg][ng][1] + b2.y);
            float2 v1 = make_float2(acc[mg][ng][2] + b2.x, acc[mg][ng][3] + b2.y);
            if (EPI == 1) {
                v0.x = 0.5f*v0.x*(1.0f + erff(v0.x*0.7071067811865475f));
                v0.y = 0.5f*v0.y*(1.0f + erff(v0.y*0.7071067811865475f));
                v1.x = 0.5f*v1.x*(1.0f + erff(v1.x*0.7071067811865475f));
                v1.y = 0.5f*v1.y*(1.0f + erff(v1.y*0.7071067811865475f));
            }
            if (EPI == 2) {
                float2 r0 = *(const float2*)&res[(size_t)row0*Nout + col];
                float2 r1 = *(const float2*)&res[(size_t)row1*Nout + col];
                v0.x += r0.x; v0.y += r0.y;
                v1.x += r1.x; v1.y += r1.y;
                *(float2*)&Cf[(size_t)row0*Nout + col] = v0;
                *(float2*)&Cf[(size_t)row1*Nout + col] = v1;
            } else {
                const int cb = (n0 + wn + ng*8) >> 1;
                uint32_t p0, p1;
                if (vf16) { p0 = packh(v0.x, v0.y);  p1 = packh(v1.x, v1.y); }
                else      { p0 = packbf(v0.x, v0.y); p1 = packbf(v1.x, v1.y); }
                Cb[(size_t)row0*(Nout >> 1) + cb + t] = p0;
                Cb[(size_t)row1*(Nout >> 1) + cb + t] = p1;
            }
        }
    }
}

// ---------------- 2b) out-proj GEMM + residual + fused LN2 ----------------
__global__ void __launch_bounds__(128) gemm_oln(const __nv_bfloat16* __restrict__ A,
                                                const __nv_bfloat16* __restrict__ W,
                                                const float* __restrict__ bias,
                                                float* __restrict__ eig,
                                                uint32_t* __restrict__ h2,
                                                const float* __restrict__ lns,
                                                const float* __restrict__ lnb) {
    extern __shared__ __align__(16) uint32_t smu[];
    uint32_t* As = smu;              // 64*68
    uint32_t* Ws = smu + 64*68;      // 128*68
    float* Hs = (float*)smu;         // 64*132 fp32 (reused after mma)
    const int tid = threadIdx.x;     // 128
    const int m0 = blockIdx.x * 64;
    const int warp = tid >> 5, lane = tid & 31;
    const int g = lane >> 2, t = lane & 3;
    const int wm = (warp >> 1) * 32, wn = (warp & 1) * 64;

    {
        const int r = tid >> 1, j0 = (tid & 1) * 8;
        const uint4* Ag = (const uint4*)(A + (size_t)(m0 + r) * 128) + j0;
        uint4* Ad = (uint4*)(As + r*68) + j0;
        #pragma unroll
        for (int j = 0; j < 8; ++j) Ad[j] = Ag[j];
        const uint4* Wg = (const uint4*)(W + (size_t)tid * 128);
        uint4* Wd = (uint4*)(Ws + tid*68);
        #pragma unroll
        for (int j = 0; j < 16; ++j) Wd[j] = Wg[j];
    }
    __syncthreads();

    float acc[2][8][4] = {};
    #pragma unroll
    for (int k = 0; k < 8; ++k) {
        const int k0 = k * 8;
        uint32_t af[2][4];
        #pragma unroll
        for (int mg = 0; mg < 2; ++mg) {
            const uint32_t* ap = As + (wm + mg*16 + g) * 68 + k0;
            af[mg][0] = ap[t];
            af[mg][1] = ap[8*68 + t];
            af[mg][2] = ap[t + 4];
            af[mg][3] = ap[8*68 + t + 4];
        }
        #pragma unroll
        for (int ng = 0; ng < 8; ++ng) {
            const uint32_t* wp = Ws + (wn + ng*8 + g) * 68 + k0;
            const uint32_t b0 = wp[t];
            const uint32_t b1 = wp[t + 4];
            mma_bf16(acc[0][ng], af[0][0], af[0][1], af[0][2], af[0][3], b0, b1);
            mma_bf16(acc[1][ng], af[1][0], af[1][1], af[1][2], af[1][3], b0, b1);
        }
    }
    __syncthreads();   // all smem reads done; Hs may now overwrite

    #pragma unroll
    for (int mg = 0; mg < 2; ++mg) {
        const int rl0 = wm + mg*16 + g, rl1 = rl0 + 8;
        #pragma unroll
        for (int ng = 0; ng < 8; ++ng) {
            const int col = wn + ng*8 + 2*t;
            float2 b2 = *(const float2*)&bias[col];
            float2 r0 = *(const float2*)&eig[(size_t)(m0 + rl0)*DD + col];
            float2 r1 = *(const float2*)&eig[(size_t)(m0 + rl1)*DD + col];
            float2 v0 = make_float2(acc[mg][ng][0] + b2.x + r0.x, acc[mg][ng][1] + b2.y + r0.y);
            float2 v1 = make_float2(acc[mg][ng][2] + b2.x + r1.x, acc[mg][ng][3] + b2.y + r1.y);
            *(float2*)&eig[(size_t)(m0 + rl0)*DD + col] = v0;
            *(float2*)&eig[(size_t)(m0 + rl1)*DD + col] = v1;
            *(float2*)&Hs[rl0*132 + col] = v0;
            *(float2*)&Hs[rl1*132 + col] = v1;
        }
    }
    __syncthreads();

    // LN2 over the 64 in-smem rows: warp w handles rows [16w, 16w+16)
    const float4 ls = *(const float4*)&lns[4*lane];
    const float4 lb = *(const float4*)&lnb[4*lane];
    for (int rl = warp*16; rl < warp*16 + 16; ++rl) {
        float4 v = *(const float4*)&Hs[rl*132 + 4*lane];
        float s = v.x + v.y + v.z + v.w;
        float q = v.x*v.x + v.y*v.y + v.z*v.z + v.w*v.w;
        #pragma unroll
        for (int o = 16; o; o >>= 1) {
            s += __shfl_xor_sync(0xffffffffu, s, o);
            q += __shfl_xor_sync(0xffffffffu, q, o);
        }
        const float mean = s * (1.0f/128.0f);
        const float var  = q * (1.0f/128.0f) - mean*mean;
        const float inv  = rsqrtf(var + 1e-5f);
        const float h0 = (v.x - mean)*inv*ls.x + lb.x;
        const float h1v = (v.y - mean)*inv*ls.y + lb.y;
        const float h2v = (v.z - mean)*inv*ls.z + lb.z;
        const float h3 = (v.w - mean)*inv*ls.w + lb.w;
        uint2 o2;
        o2.x = packbf(h0, h1v);
        o2.y = packbf(h2v, h3);
        *(uint2*)&h2[(size_t)(m0 + rl)*64 + 2*lane] = o2;
    }
}

// ---------------- 3) flash attention: fused QK->exp->PV per 16-key chunk ----------------
// Registers minimized: sf transient (4), ef 8 live. V arrives f16 (byte_perm staging).
#define KSP 12
#define VTP 36

__global__ void __launch_bounds__(128, 6) attn_kernel(const uint32_t* __restrict__ qkv,
                                                      uint32_t* __restrict__ att,
                                                      const int* __restrict__ length) {
    const int bh   = blockIdx.y;
    const int b    = bh >> 3, h = bh & 7;
    const int warp = threadIdx.x >> 5;
    const int lane = threadIdx.x & 31;
    const int g    = lane >> 2, t = lane & 3;
    const int qb   = blockIdx.x * 128 + warp * 32;
    const int len  = length[b];

    __shared__ __align__(16) uint32_t Ks[64 * KSP];
    __shared__ __align__(16) uint32_t Vt[24 * VTP];   // rows 0..15 V(f16), 16 ones, 17..23 zeros

    const uint32_t* base = qkv + (size_t)b * NN * 192;

    // ones/zeros rows for the l-sum column (constant across tiles)
    for (int i = threadIdx.x; i < 8*VTP; i += 128)
        Vt[16*VTP + i] = (i < VTP) ? 0x3C003C00u : 0u;

    uint32_t qf[2][4];
    #pragma unroll
    for (int mg = 0; mg < 2; ++mg) {
        const uint32_t* q0 = base + (size_t)(qb + mg*16 + g)*192 + h*8;
        const uint32_t* q1 = q0 + 8*192;
        qf[mg][0] = q0[t];
        qf[mg][1] = q1[t];
        qf[mg][2] = q0[t + 4];
        qf[mg][3] = q1[t + 4];
    }

    float of[2][2][4] = {};
    float of2[2][4] = {};     // l accumulators via ones-column mma

    for (int k0 = 0; k0 < len; k0 += 64) {
        __syncthreads();
        {
            // K: one uint4 copy (bf16)
            const int key = threadIdx.x >> 1, c4 = (threadIdx.x & 1) * 4;
            const uint4 kv = *(const uint4*)(base + (size_t)(k0 + key)*192 + 64 + h*8 + c4);
            *(uint4*)(Ks + key*KSP + c4) = kv;
            // V transposed: f16 in gmem, pure byte_perm pair-merge (low = even key)
            const int kp = threadIdx.x & 31, dg = (threadIdx.x >> 5) * 4;
            const uint32_t* va = base + (size_t)(k0 + 2*kp)*192 + 128 + h*8 + (dg >> 1);
            const uint2 a = *(const uint2*)va;
            const uint2 c = *(const uint2*)(va + 192);
            Vt[(dg+0)*VTP + kp] = __byte_perm(a.x, c.x, 0x5410);
            Vt[(dg+1)*VTP + kp] = __byte_perm(a.x, c.x, 0x7632);
            Vt[(dg+2)*VTP + kp] = __byte_perm(a.y, c.y, 0x5410);
            Vt[(dg+3)*VTP + kp] = __byte_perm(a.y, c.y, 0x7632);
        }
        __syncthreads();

        const bool tail = (k0 + 64 > len);
        #pragma unroll
        for (int kg = 0; kg < 4; ++kg) {
            // --- QK + exp for the two 8-key groups of this chunk ---
            uint32_t ef[2][4];
            #pragma unroll
            for (int half = 0; half < 2; ++half) {
                const int ng = 2*kg + half;
                const int key = ng*8 + g;
                const uint32_t b0 = Ks[key*KSP + t];
                const uint32_t b1 = Ks[key*KSP + t + 4];
                #pragma unroll
                for (int mg = 0; mg < 2; ++mg) {
                    float sf[4] = {0.f, 0.f, 0.f, 0.f};
                    mma_bf16(sf, qf[mg][0], qf[mg][1], qf[mg][2], qf[mg][3], b0, b1);
                    if (tail) {        // uniform branch; -1e30 -> f16 -inf -> exp 0
                        const int kc0 = k0 + ng*8 + 2*t;
                        if (kc0 >= len)     { sf[0] = -1e30f; sf[2] = -1e30f; }
                        if (kc0 + 1 >= len) { sf[1] = -1e30f; sf[3] = -1e30f; }
                    }
                    ef[mg][2*half + 0] = exp2h2(sf[0], sf[1]);
                    ef[mg][2*half + 1] = exp2h2(sf[2], sf[3]);
                }
            }
            // --- PV + l for this chunk ---
            uint32_t vb[3][2];
            #pragma unroll
            for (int nd = 0; nd < 3; ++nd) {
                vb[nd][0] = Vt[(nd*8 + g)*VTP + kg*8 + t];
                vb[nd][1] = Vt[(nd*8 + g)*VTP + kg*8 + t + 4];
            }
            #pragma unroll
            for (int mg = 0; mg < 2; ++mg) {
                mma_f16(of[mg][0], ef[mg][0], ef[mg][1], ef[mg][2], ef[mg][3], vb[0][0], vb[0][1]);
                mma_f16(of[mg][1], ef[mg][0], ef[mg][1], ef[mg][2], ef[mg][3], vb[1][0], vb[1][1]);
                mma_f16(of2[mg],   ef[mg][0], ef[mg][1], ef[mg][2], ef[mg][3], vb[2][0], vb[2][1]);
            }
        }
    }

    // l lives in column 0 (lanes t==0); broadcast within each row quad
    #pragma unroll
    for (int mg = 0; mg < 2; ++mg) {
        const float l0 = __shfl_sync(0xffffffffu, of2[mg][0], lane & ~3);
        const float l1 = __shfl_sync(0xffffffffu, of2[mg][2], lane & ~3);
        const float inv0 = 1.0f / l0;
        const float inv1 = 1.0f / l1;
        const int r0 = qb + mg*16 + g, r1 = r0 + 8;
        #pragma unroll
        for (int nd = 0; nd < 2; ++nd) {
            const int ci = h*8 + nd*4 + t;
            att[(size_t)(b*NN + r0)*64 + ci] = packbf(of[mg][nd][0]*inv0, of[mg][nd][1]*inv0);
            att[(size_t)(b*NN + r1)*64 + ci] = packbf(of[mg][nd][2]*inv1, of[mg][nd][3]*inv1);
        }
    }
}

// ---------------- 4) pooled decoders: stage 1 (parallel column sums) ----------------
__global__ void colsum_kernel(const int* __restrict__ length) {
    const int b = blockIdx.x >> 3, seg = blockIdx.x & 7;
    const int d = threadIdx.x;
    const int len = length[b];
    const int n0 = seg * 128;
    const int n1 = min(n0 + 128, len);
    const float* p = g_eig + (size_t)b*NN*DD + d;
    float s = 0.f;
    for (int n = n0; n < n1; ++n) s += p[(size_t)n*DD];
    g_part[(b*8 + seg)*DD + d] = s;
}

// ---------------- 5) pooled decoders: stage 2 ----------------
__global__ void pooled_kernel(const int* __restrict__ length,
                              const float* __restrict__ Wsca, const float* __restrict__ bsca,
                              const float* __restrict__ Wwav, const float* __restrict__ bwav,
                              const float* __restrict__ Wscl, const float* __restrict__ bscl) {
    __shared__ float ssum[128];
    __shared__ float co[20];
    const int b = blockIdx.x, t = threadIdx.x;
    const int len = length[b];
    {
        const float* pp = g_part + b*8*DD + t;
        float s = 0.f;
        #pragma unroll
        for (int seg = 0; seg < 8; ++seg) s += pp[seg*DD];
        ssum[t] = s;
    }
    __syncthreads();
    if (t < 20) {
        const float* W; float bb;
        if (t < 8)        { W = Wsca + t*128;      bb = bsca[t]; }
        else if (t < 16)  { W = Wwav + (t-8)*128;  bb = bwav[t-8]; }
        else              { W = Wscl + (t-16)*128; bb = bscl[t-16]; }
        float a = 0.f;
        #pragma unroll 8
        for (int k = 0; k < 128; ++k) a += ssum[k] * W[k];
        const float lenf = (float)len;
        a = (a + lenf*bb) / (lenf + 1e-8f);
        co[t] = 1.0f / (1.0f + expf(-a));
    }
    __syncthreads();
    if (t == 0) {
        float s1 = 0.f, s2 = 0.f;
        for (int i = 0; i < 8; ++i) { s1 += co[i]; s2 += co[8+i]; }
        const float i1 = 1.0f/(s1 + 1e-8f), i2 = 1.0f/(s2 + 1e-8f);
        for (int i = 0; i < 8; ++i) {
            g_coe[b*20 + i]     = co[i]   * i1;
            g_coe[b*20 + 8 + i] = co[8+i] * i2;
        }
        for (int i = 0; i < 4; ++i) g_coe[b*20 + 16 + i] = co[16+i] * 2.0f;
    }
}

// ---------------- 6) Chebyshev bases + tight-frame output ----------------
__global__ void final_kernel(const float* __restrict__ eva, float* __restrict__ out) {
    const int idx = blockIdx.x*256 + threadIdx.x;
    if (idx >= ROWS) return;
    const int b = idx / NN;
    const float ev = eva[idx];
    const float* coe = g_coe + b*20;

    float y = ev - 1.0f;
    float te = 1.0f, to = y;
    float s = coe[0] * 0.5f * (1.0f - to);
    #pragma unroll
    for (int k = 1; k < 8; ++k) {
        te = 2.0f*y*to - te;
        to = 2.0f*y*te - to;
        s += coe[k] * 0.5f * (1.0f - to);
    }
    float w[4];
    #pragma unroll
    for (int j = 0; j < 4; ++j) {
        float f = ev * coe[16 + j];
        if (f > 2.0f) f = 0.0f;
        const float yj = f - 1.0f;
        float te2 = 1.0f, to2 = yj;
        float a = coe[8] * 0.5f * (1.0f - te2);
        #pragma unroll
        for (int k = 1; k < 8; ++k) {
            te2 = 2.0f*yj*to2 - te2;
            to2 = 2.0f*yj*te2 - to2;
            a += coe[8 + k] * 0.5f * (1.0f - te2);
        }
        w[j] = a;
    }
    const float nrm = sqrtf(s*s + w[0]*w[0] + w[1]*w[1] + w[2]*w[2] + w[3]*w[3]);
    const float inv = 1.0f / (nrm + 1e-8f);
    float* o = out + (size_t)idx * 5;
    o[0] = s*inv; o[1] = w[0]*inv; o[2] = w[1]*inv; o[3] = w[2]*inv; o[4] = w[3]*inv;
}

// ---------------- host launch ----------------
extern "C" void kernel_launch(void* const* d_in, const int* in_sizes, int n_in,
                              void* d_out, int out_size) {
    const float* eva    = (const float*)d_in[1];
    const int*   length = (const int*)  d_in[2];
    const float* eigW   = (const float*)d_in[3];
    const float* eigB   = (const float*)d_in[4];
    const float* ln1s   = (const float*)d_in[5];
    const float* ln1b   = (const float*)d_in[6];
    const float* ln2s   = (const float*)d_in[7];
    const float* ln2b   = (const float*)d_in[8];
    const float* qkvW   = (const float*)d_in[9];
    const float* qkvB   = (const float*)d_in[10];
    const float* outW   = (const float*)d_in[11];
    const float* outB   = (const float*)d_in[12];
    const float* f1W    = (const float*)d_in[13];
    const float* f1B    = (const float*)d_in[14];
    const float* f2W    = (const float*)d_in[15];
    const float* f2B    = (const float*)d_in[16];
    const float* dsW    = (const float*)d_in[17];
    const float* dsB    = (const float*)d_in[18];
    const float* dwW    = (const float*)d_in[19];
    const float* dwB    = (const float*)d_in[20];
    const float* dlW    = (const float*)d_in[21];
    const float* dlB    = (const float*)d_in[22];

    float *p_eig, *p_qkvbias;
    void *p_h1, *p_qkv4, *p_att4, *p_h2, *p_f14, *p_wqkv, *p_wout, *p_wf1, *p_wf2;
    cudaGetSymbolAddress((void**)&p_eig, g_eig);
    cudaGetSymbolAddress((void**)&p_qkvbias, g_qkvbias);
    cudaGetSymbolAddress(&p_h1,   g_h1);
    cudaGetSymbolAddress(&p_qkv4, g_qkv4);
    cudaGetSymbolAddress(&p_att4, g_att4);
    cudaGetSymbolAddress(&p_h2,   g_h2);
    cudaGetSymbolAddress(&p_f14,  g_f14);
    cudaGetSymbolAddress(&p_wqkv, g_wqkv4);
    cudaGetSymbolAddress(&p_wout, g_wout4);
    cudaGetSymbolAddress(&p_wf1,  g_wf14);
    cudaGetSymbolAddress(&p_wf2,  g_wf24);
    (void)in_sizes; (void)n_in; (void)out_size;

    const int ENC_SMEM = (128*132 + 4*132) * (int)sizeof(float);
    const int OLN_SMEM = (64*68 + 128*68) * (int)sizeof(uint32_t);
    cudaFuncSetAttribute(encode_kernel, cudaFuncAttributeMaxDynamicSharedMemorySize, ENC_SMEM);
    cudaFuncSetAttribute(gemm_oln,      cudaFuncAttributeMaxDynamicSharedMemorySize, OLN_SMEM);

    // 0) weights -> bf16 (q pre-scaled)
    wconv_kernel<<<64, 256>>>(qkvW, qkvB, outW, f1W, f2W);
    // 1) encode + LN1 -> g_eig (fp32), g_h1 (bf16)
    encode_kernel<<<ROWS/64, 128, ENC_SMEM>>>(eva, eigW, eigB, ln1s, ln1b);
    // 2) QKV -> g_qkv4 (q|k bf16, v f16)
    gemm_bb<3><<<dim3(6, ROWS/64), 128>>>((const __nv_bfloat16*)p_h1, (const __nv_bfloat16*)p_wqkv,
                                          p_qkvbias, nullptr, (uint32_t*)p_qkv4, nullptr, 3*DD);
    // 3) attention -> g_att4 (bf16)
    attn_kernel<<<dim3(NN/128, BB*HH), 128>>>((const uint32_t*)p_qkv4, (uint32_t*)p_att4, length);
    // 4) out proj + residual + LN2 -> g_eig (fp32), g_h2 (bf16)
    gemm_oln<<<ROWS/64, 128, OLN_SMEM>>>((const __nv_bfloat16*)p_att4, (const __nv_bfloat16*)p_wout,
                                         outB, p_eig, (uint32_t*)p_h2, ln2s, ln2b);
    // 5) FFN1 (gelu) -> g_f14 (bf16)
    gemm_bb<1><<<dim3(2, ROWS/64), 128>>>((const __nv_bfloat16*)p_h2, (const __nv_bfloat16*)p_wf1,
                                          f1B, nullptr, (uint32_t*)p_f14, nullptr, DD);
    // 6) FFN2 + residual -> g_eig (fp32)
    gemm_bb<2><<<dim3(2, ROWS/64), 128>>>((const __nv_bfloat16*)p_f14, (const __nv_bfloat16*)p_wf2,
                                          f2B, p_eig, nullptr, p_eig, DD);
    // 7) pooled decoders -> g_coe
    colsum_kernel<<<BB*8, 128>>>(length);
    pooled_kernel<<<BB, 128>>>(length, dsW, dsB, dwW, dwB, dlW, dlB);
    // 8) Chebyshev + normalize -> d_out
    final_kernel<<<(ROWS + 255)/256, 256>>>(eva, (float*)d_out);
}

// round 15
// speedup vs baseline: 1.0430x; 1.0430x over previous
#include <cuda_runtime.h>
#include <cuda_bf16.h>
#include <cuda_fp16.h>
#include <math.h>
#include <stdint.h>

#define BB 16
#define NN 1024
#define DD 128
#define HH 8
#define NUMN 8
#define NUMJ 4
#define ROWS (BB*NN)   /* 16384 */

// ---------------- scratch (device globals; no allocation) ----------------
__device__ float g_eig[ROWS*DD];          // fp32 residual stream
__device__ float g_part[BB*8*DD];         // pooled partial sums
__device__ float g_coe[BB*20];
__device__ float g_qkvbias[3*DD];         // q-part pre-scaled
__device__ uint4 g_h1[ROWS*DD/8];         // bf16 LN1 output
__device__ uint4 g_qkv4[ROWS*3*DD/8];     // q|k bf16, v f16 (q pre-scaled)
__device__ uint4 g_att4[ROWS*DD/8];       // bf16 attention output
__device__ uint4 g_h2[ROWS*DD/8];         // bf16 LN2 output
__device__ uint4 g_f14[ROWS*DD/8];        // bf16 ffn intermediate
__device__ uint4 g_wqkv4[3*DD*DD/8];      // bf16 weights
__device__ uint4 g_wout4[DD*DD/8];
__device__ uint4 g_wf14[DD*DD/8];
__device__ uint4 g_wf24[DD*DD/8];

#define QSCALE (0.25f * 1.4426950408889634f)   /* 1/sqrt(dh) * log2(e) */

__device__ __forceinline__ uint32_t packbf(float lo, float hi) {
    __nv_bfloat162 v = __floats2bfloat162_rn(lo, hi);
    return *reinterpret_cast<uint32_t*>(&v);
}
__device__ __forceinline__ void mma_bf16(float c[4],
                                         uint32_t a0, uint32_t a1, uint32_t a2, uint32_t a3,
                                         uint32_t b0, uint32_t b1) {
    asm("mma.sync.aligned.m16n8k16.row.col.f32.bf16.bf16.f32 "
        "{%0,%1,%2,%3},{%4,%5,%6,%7},{%8,%9},{%0,%1,%2,%3};"
        : "+f"(c[0]), "+f"(c[1]), "+f"(c[2]), "+f"(c[3])
        : "r"(a0), "r"(a1), "r"(a2), "r"(a3), "r"(b0), "r"(b1));
}
__device__ __forceinline__ void mma_f16(float c[4],
                                        uint32_t a0, uint32_t a1, uint32_t a2, uint32_t a3,
                                        uint32_t b0, uint32_t b1) {
    asm("mma.sync.aligned.m16n8k16.row.col.f32.f16.f16.f32 "
        "{%0,%1,%2,%3},{%4,%5,%6,%7},{%8,%9},{%0,%1,%2,%3};"
        : "+f"(c[0]), "+f"(c[1]), "+f"(c[2]), "+f"(c[3])
        : "r"(a0), "r"(a1), "r"(a2), "r"(a3), "r"(b0), "r"(b1));
}
__device__ __forceinline__ uint32_t exp2h2(float lo, float hi) {
    __half2 h = h2exp2(__floats2half2_rn(lo, hi));   // 1 MUFU per 2 values
    return *reinterpret_cast<uint32_t*>(&h);
}
__device__ __forceinline__ uint32_t packh(float lo, float hi) {
    __half2 h = __floats2half2_rn(lo, hi);
    return *reinterpret_cast<uint32_t*>(&h);
}

// ---------------- 0) one-time weight conversion to bf16 ----------------
__global__ void wconv_kernel(const float* __restrict__ qkvW, const float* __restrict__ qkvB,
                             const float* __restrict__ outW, const float* __restrict__ f1W,
                             const float* __restrict__ f2W) {
    const int stride = gridDim.x * blockDim.x;
    const int i0 = blockIdx.x * blockDim.x + threadIdx.x;
    __nv_bfloat16* wq = (__nv_bfloat16*)g_wqkv4;
    __nv_bfloat16* wo = (__nv_bfloat16*)g_wout4;
    __nv_bfloat16* w1 = (__nv_bfloat16*)g_wf14;
    __nv_bfloat16* w2 = (__nv_bfloat16*)g_wf24;
    for (int i = i0; i < 3*DD*DD; i += stride) {
        float v = qkvW[i];
        if (i < DD*DD) v *= QSCALE;           // fold Q scale into Wq
        wq[i] = __float2bfloat16(v);
    }
    for (int i = i0; i < DD*DD; i += stride) {
        wo[i] = __float2bfloat16(outW[i]);
        w1[i] = __float2bfloat16(f1W[i]);
        w2[i] = __float2bfloat16(f2W[i]);
    }
    if (i0 < 3*DD) g_qkvbias[i0] = qkvB[i0] * (i0 < DD ? QSCALE : 1.0f);
}

// ---------------- 1) sine encoding + projection + fused LN1 (4 rows/iter) ----------------
__global__ void encode_kernel(const float* __restrict__ eva,
                              const float* __restrict__ W,
                              const float* __restrict__ bias,
                              const float* __restrict__ lns,
                              const float* __restrict__ lnb) {
    extern __shared__ float sm[];
    float* Wsh  = sm;            // [128][132]
    float* eeig = sm + 128*132;  // [4][132]
    __shared__ float red1[4][4];
    __shared__ float red2[4][4];
    const int t = threadIdx.x;   // 128
    const int wid = t >> 5, lane = t & 31;

    for (int idx = t; idx < 128*129; idx += 128) {
        int d = idx / 129, i = idx % 129;
        Wsh[d*132 + i] = W[idx];
    }
    const float bs = bias[t];
    const float s1 = lns[t], b1 = lnb[t];
    const int f = t & 63, rr = t >> 6;
    const float divt = expf(-(float)(2*f) * (9.210340371976184f / 128.0f));
    const int row0 = blockIdx.x * 64;
    uint32_t* h1 = (uint32_t*)g_h1;
    __syncthreads();

    for (int r4 = 0; r4 < 64; r4 += 4) {
        #pragma unroll
        for (int j = 0; j < 2; ++j) {
            const int r = rr + 2*j;
            const float e = eva[row0 + r4 + r];
            float pe = e * 100.0f * divt;
            float s, c;
            sincosf(pe, &s, &c);
            eeig[r*132 + 1 + f]  = s;
            eeig[r*132 + 65 + f] = c;
            if (f == 0) eeig[r*132] = e;
        }
        __syncthreads();

        float acc[4] = {bs, bs, bs, bs};
        const float4* Wv = (const float4*)(Wsh + t*132);
        const float4* E0 = (const float4*)(eeig);
        const float4* E1 = (const float4*)(eeig + 132);
        const float4* E2 = (const float4*)(eeig + 264);
        const float4* E3 = (const float4*)(eeig + 396);
        #pragma unroll 4
        for (int i4 = 0; i4 < 32; ++i4) {
            float4 w = Wv[i4];
            float4 e0 = E0[i4], e1 = E1[i4], e2 = E2[i4], e3 = E3[i4];
            acc[0] += w.x*e0.x + w.y*e0.y + w.z*e0.z + w.w*e0.w;
            acc[1] += w.x*e1.x + w.y*e1.y + w.z*e1.z + w.w*e1.w;
            acc[2] += w.x*e2.x + w.y*e2.y + w.z*e2.z + w.w*e2.w;
            acc[3] += w.x*e3.x + w.y*e3.y + w.z*e3.z + w.w*e3.w;
        }
        const float wlast = Wsh[t*132 + 128];
        #pragma unroll
        for (int r = 0; r < 4; ++r) acc[r] += wlast * eeig[r*132 + 128];

        // store fp32 + LN over 4 rows
        #pragma unroll
        for (int r = 0; r < 4; ++r) {
            g_eig[(size_t)(row0 + r4 + r)*DD + t] = acc[r];
            float x = acc[r];
            #pragma unroll
            for (int o = 16; o; o >>= 1) x += __shfl_xor_sync(0xffffffffu, x, o);
            if (lane == 0) red1[r][wid] = x;
        }
        __syncthreads();
        float dd[4];
        #pragma unroll
        for (int r = 0; r < 4; ++r) {
            const float mean = (red1[r][0]+red1[r][1]+red1[r][2]+red1[r][3]) * (1.0f/128.0f);
            dd[r] = acc[r] - mean;
            float q = dd[r] * dd[r];
            #pragma unroll
            for (int o = 16; o; o >>= 1) q += __shfl_xor_sync(0xffffffffu, q, o);
            if (lane == 0) red2[r][wid] = q;
        }
        __syncthreads();
        #pragma unroll
        for (int r = 0; r < 4; ++r) {
            const float var = (red2[r][0]+red2[r][1]+red2[r][2]+red2[r][3]) * (1.0f/128.0f);
            const float h = dd[r] * rsqrtf(var + 1e-5f) * s1 + b1;
            const float hh = __shfl_down_sync(0xffffffffu, h, 1);
            if (!(t & 1)) h1[(row0 + r4 + r)*64 + (t >> 1)] = packbf(h, hh);
        }
        __syncthreads();
    }
}

// ---------------- 2) bf16 GEMM, copy-only staging ----------------
// EPI 0: bf16 out; 1: gelu + bf16 out; 2: residual + fp32 out;
// EPI 3: qkv -> bf16 out for q|k columns, f16 out for v columns (n0 >= 256)
template <int EPI>
__global__ void __launch_bounds__(128) gemm_bb(const __nv_bfloat16* __restrict__ A,
                                               const __nv_bfloat16* __restrict__ W,
                                               const float* __restrict__ bias,
                                               const float* __restrict__ res,
                                               uint32_t* __restrict__ Cb,
                                               float* __restrict__ Cf,
                                               int Nout) {
    __shared__ __align__(16) uint32_t As[64*68];
    __shared__ __align__(16) uint32_t Ws[64*68];
    const int tid  = threadIdx.x;          // 128
    const int m0   = blockIdx.y * 64;
    const int n0   = blockIdx.x * 64;
    const int warp = tid >> 5, lane = tid & 31;
    const int g = lane >> 2, t = lane & 3;
    const int wm = (warp >> 1) * 32, wn = (warp & 1) * 32;

    {
        const int r = tid >> 1, j0 = (tid & 1) * 8;
        const uint4* Ag = (const uint4*)(A + (size_t)(m0 + r) * 128) + j0;
        const uint4* Wg = (const uint4*)(W + (size_t)(n0 + r) * 128) + j0;
        uint4* Ad = (uint4*)(As + r*68) + j0;
        uint4* Wd = (uint4*)(Ws + r*68) + j0;
        #pragma unroll
        for (int j = 0; j < 8; ++j) { Ad[j] = Ag[j]; Wd[j] = Wg[j]; }
    }
    __syncthreads();

    float acc[2][4][4] = {};
    #pragma unroll
    for (int k = 0; k < 8; ++k) {
        const int k0 = k * 8;
        uint32_t af[2][4];
        #pragma unroll
        for (int mg = 0; mg < 2; ++mg) {
            const uint32_t* ap = As + (wm + mg*16 + g) * 68 + k0;
            af[mg][0] = ap[t];
            af[mg][1] = ap[8*68 + t];
            af[mg][2] = ap[t + 4];
            af[mg][3] = ap[8*68 + t + 4];
        }
        #pragma unroll
        for (int ng = 0; ng < 4; ++ng) {
            const uint32_t* wp = Ws + (wn + ng*8 + g) * 68 + k0;
            const uint32_t b0 = wp[t];
            const uint32_t b1 = wp[t + 4];
            mma_bf16(acc[0][ng], af[0][0], af[0][1], af[0][2], af[0][3], b0, b1);
            mma_bf16(acc[1][ng], af[1][0], af[1][1], af[1][2], af[1][3], b0, b1);
        }
    }

    const bool vf16 = (EPI == 3) && (n0 >= 256);   // V block -> f16 packing
    #pragma unroll
    for (int mg = 0; mg < 2; ++mg) {
        const int row0 = m0 + wm + mg*16 + g;
        const int row1 = row0 + 8;
        #pragma unroll
        for (int ng = 0; ng < 4; ++ng) {
            const int col = n0 + wn + ng*8 + 2*t;
            float2 b2 = *(const float2*)&bias[col];
            float2 v0 = make_float2(acc[mg][ng][0] + b2.x, acc[mg][ng][1] + b2.y);
            float2 v1 = make_float2(acc[mg][ng][2] + b2.x, acc[mg][ng][3] + b2.y);
            if (EPI == 1) {
                v0.x = 0.5f*v0.x*(1.0f + erff(v0.x*0.7071067811865475f));
                v0.y = 0.5f*v0.y*(1.0f + erff(v0.y*0.7071067811865475f));
                v1.x = 0.5f*v1.x*(1.0f + erff(v1.x*0.7071067811865475f));
                v1.y = 0.5f*v1.y*(1.0f + erff(v1.y*0.7071067811865475f));
            }
            if (EPI == 2) {
                float2 r0 = *(const float2*)&res[(size_t)row0*Nout + col];
                float2 r1 = *(const float2*)&res[(size_t)row1*Nout + col];
                v0.x += r0.x; v0.y += r0.y;
                v1.x += r1.x; v1.y += r1.y;
                *(float2*)&Cf[(size_t)row0*Nout + col] = v0;
                *(float2*)&Cf[(size_t)row1*Nout + col] = v1;
            } else {
                const int cb = (n0 + wn + ng*8) >> 1;
                uint32_t p0, p1;
                if (vf16) { p0 = packh(v0.x, v0.y);  p1 = packh(v1.x, v1.y); }
                else      { p0 = packbf(v0.x, v0.y); p1 = packbf(v1.x, v1.y); }
                Cb[(size_t)row0*(Nout >> 1) + cb + t] = p0;
                Cb[(size_t)row1*(Nout >> 1) + cb + t] = p1;
            }
        }
    }
}

// ---------------- 2b) out-proj GEMM + residual + fused LN2 ----------------
__global__ void __launch_bounds__(128) gemm_oln(const __nv_bfloat16* __restrict__ A,
                                                const __nv_bfloat16* __restrict__ W,
                                                const float* __restrict__ bias,
                                                float* __restrict__ eig,
                                                uint32_t* __restrict__ h2,
                                                const float* __restrict__ lns,
                                                const float* __restrict__ lnb) {
    extern __shared__ __align__(16) uint32_t smu[];
    uint32_t* As = smu;              // 64*68
    uint32_t* Ws = smu + 64*68;      // 128*68
    float* Hs = (float*)smu;         // 64*132 fp32 (reused after mma)
    const int tid = threadIdx.x;     // 128
    const int m0 = blockIdx.x * 64;
    const int warp = tid >> 5, lane = tid & 31;
    const int g = lane >> 2, t = lane & 3;
    const int wm = (warp >> 1) * 32, wn = (warp & 1) * 64;

    {
        const int r = tid >> 1, j0 = (tid & 1) * 8;
        const uint4* Ag = (const uint4*)(A + (size_t)(m0 + r) * 128) + j0;
        uint4* Ad = (uint4*)(As + r*68) + j0;
        #pragma unroll
        for (int j = 0; j < 8; ++j) Ad[j] = Ag[j];
        const uint4* Wg = (const uint4*)(W + (size_t)tid * 128);
        uint4* Wd = (uint4*)(Ws + tid*68);
        #pragma unroll
        for (int j = 0; j < 16; ++j) Wd[j] = Wg[j];
    }
    __syncthreads();

    float acc[2][8][4] = {};
    #pragma unroll
    for (int k = 0; k < 8; ++k) {
        const int k0 = k * 8;
        uint32_t af[2][4];
        #pragma unroll
        for (int mg = 0; mg < 2; ++mg) {
            const uint32_t* ap = As + (wm + mg*16 + g) * 68 + k0;
            af[mg][0] = ap[t];
            af[mg][1] = ap[8*68 + t];
            af[mg][2] = ap[t + 4];
            af[mg][3] = ap[8*68 + t + 4];
        }
        #pragma unroll
        for (int ng = 0; ng < 8; ++ng) {
            const uint32_t* wp = Ws + (wn + ng*8 + g) * 68 + k0;
            const uint32_t b0 = wp[t];
            const uint32_t b1 = wp[t + 4];
            mma_bf16(acc[0][ng], af[0][0], af[0][1], af[0][2], af[0][3], b0, b1);
            mma_bf16(acc[1][ng], af[1][0], af[1][1], af[1][2], af[1][3], b0, b1);
        }
    }
    __syncthreads();   // all smem reads done; Hs may now overwrite

    #pragma unroll
    for (int mg = 0; mg < 2; ++mg) {
        const int rl0 = wm + mg*16 + g, rl1 = rl0 + 8;
        #pragma unroll
        for (int ng = 0; ng < 8; ++ng) {
            const int col = wn + ng*8 + 2*t;
            float2 b2 = *(const float2*)&bias[col];
            float2 r0 = *(const float2*)&eig[(size_t)(m0 + rl0)*DD + col];
            float2 r1 = *(const float2*)&eig[(size_t)(m0 + rl1)*DD + col];
            float2 v0 = make_float2(acc[mg][ng][0] + b2.x + r0.x, acc[mg][ng][1] + b2.y + r0.y);
            float2 v1 = make_float2(acc[mg][ng][2] + b2.x + r1.x, acc[mg][ng][3] + b2.y + r1.y);
            *(float2*)&eig[(size_t)(m0 + rl0)*DD + col] = v0;
            *(float2*)&eig[(size_t)(m0 + rl1)*DD + col] = v1;
            *(float2*)&Hs[rl0*132 + col] = v0;
            *(float2*)&Hs[rl1*132 + col] = v1;
        }
    }
    __syncthreads();

    // LN2 over the 64 in-smem rows: warp w handles rows [16w, 16w+16)
    const float4 ls = *(const float4*)&lns[4*lane];
    const float4 lb = *(const float4*)&lnb[4*lane];
    for (int rl = warp*16; rl < warp*16 + 16; ++rl) {
        float4 v = *(const float4*)&Hs[rl*132 + 4*lane];
        float s = v.x + v.y + v.z + v.w;
        float q = v.x*v.x + v.y*v.y + v.z*v.z + v.w*v.w;
        #pragma unroll
        for (int o = 16; o; o >>= 1) {
            s += __shfl_xor_sync(0xffffffffu, s, o);
            q += __shfl_xor_sync(0xffffffffu, q, o);
        }
        const float mean = s * (1.0f/128.0f);
        const float var  = q * (1.0f/128.0f) - mean*mean;
        const float inv  = rsqrtf(var + 1e-5f);
        const float h0 = (v.x - mean)*inv*ls.x + lb.x;
        const float h1v = (v.y - mean)*inv*ls.y + lb.y;
        const float h2v = (v.z - mean)*inv*ls.z + lb.z;
        const float h3 = (v.w - mean)*inv*ls.w + lb.w;
        uint2 o2;
        o2.x = packbf(h0, h1v);
        o2.y = packbf(h2v, h3);
        *(uint2*)&h2[(size_t)(m0 + rl)*64 + 2*lane] = o2;
    }
}

// ---------------- 3) flash attention: pipelined staging + fused QK->exp->PV ----------------
// Register double-buffer: next tile's K/V gmem loads issue before current tile's compute.
#define KSP 12
#define VTP 36

__global__ void __launch_bounds__(128, 6) attn_kernel(const uint32_t* __restrict__ qkv,
                                                      uint32_t* __restrict__ att,
                                                      const int* __restrict__ length) {
    const int bh   = blockIdx.y;
    const int b    = bh >> 3, h = bh & 7;
    const int warp = threadIdx.x >> 5;
    const int lane = threadIdx.x & 31;
    const int g    = lane >> 2, t = lane & 3;
    const int qb   = blockIdx.x * 128 + warp * 32;
    const int len  = length[b];

    __shared__ __align__(16) uint32_t Ks[64 * KSP];
    __shared__ __align__(16) uint32_t Vt[24 * VTP];   // rows 0..15 V(f16), 16 ones, 17..23 zeros

    const uint32_t* base = qkv + (size_t)b * NN * 192;

    // ones/zeros rows for the l-sum column (constant across tiles)
    for (int i = threadIdx.x; i < 8*VTP; i += 128)
        Vt[16*VTP + i] = (i < VTP) ? 0x3C003C00u : 0u;

    uint32_t qf[2][4];
    #pragma unroll
    for (int mg = 0; mg < 2; ++mg) {
        const uint32_t* q0 = base + (size_t)(qb + mg*16 + g)*192 + h*8;
        const uint32_t* q1 = q0 + 8*192;
        qf[mg][0] = q0[t];
        qf[mg][1] = q1[t];
        qf[mg][2] = q0[t + 4];
        qf[mg][3] = q1[t + 4];
    }

    // staging addresses (loop-invariant)
    const int skey = threadIdx.x >> 1, sc4 = (threadIdx.x & 1) * 4;
    const uint32_t* kptr = base + (size_t)skey*192 + 64 + h*8 + sc4;
    const int skp = threadIdx.x & 31, sdg = (threadIdx.x >> 5) * 4;
    const uint32_t* vptr = base + (size_t)(2*skp)*192 + 128 + h*8 + (sdg >> 1);

    float of[2][2][4] = {};
    float of2[2][4] = {};     // l accumulators via ones-column mma

    // prologue: load tile 0
    uint4 kreg = *(const uint4*)kptr;
    uint2 areg = *(const uint2*)vptr;
    uint2 creg = *(const uint2*)(vptr + 192);

    for (int k0 = 0; k0 < len; k0 += 64) {
        __syncthreads();   // prev tile's smem fully consumed
        // store held registers to smem
        *(uint4*)(Ks + skey*KSP + sc4) = kreg;
        Vt[(sdg+0)*VTP + skp] = __byte_perm(areg.x, creg.x, 0x5410);
        Vt[(sdg+1)*VTP + skp] = __byte_perm(areg.x, creg.x, 0x7632);
        Vt[(sdg+2)*VTP + skp] = __byte_perm(areg.y, creg.y, 0x5410);
        Vt[(sdg+3)*VTP + skp] = __byte_perm(areg.y, creg.y, 0x7632);
        // prefetch next tile (latency overlaps this tile's compute)
        if (k0 + 64 < len) {
            const size_t off = (size_t)(k0 + 64) * 192;
            kreg = *(const uint4*)(kptr + off);
            areg = *(const uint2*)(vptr + off);
            creg = *(const uint2*)(vptr + off + 192);
        }
        __syncthreads();

        const bool tail = (k0 + 64 > len);
        #pragma unroll
        for (int kg = 0; kg < 4; ++kg) {
            // --- QK + exp for the two 8-key groups of this chunk ---
            uint32_t ef[2][4];
            #pragma unroll
            for (int half = 0; half < 2; ++half) {
                const int ng = 2*kg + half;
                const int key = ng*8 + g;
                const uint32_t b0 = Ks[key*KSP + t];
                const uint32_t b1 = Ks[key*KSP + t + 4];
                #pragma unroll
                for (int mg = 0; mg < 2; ++mg) {
                    float sf[4] = {0.f, 0.f, 0.f, 0.f};
                    mma_bf16(sf, qf[mg][0], qf[mg][1], qf[mg][2], qf[mg][3], b0, b1);
                    if (tail) {        // uniform branch; -1e30 -> f16 -inf -> exp 0
                        const int kc0 = k0 + ng*8 + 2*t;
                        if (kc0 >= len)     { sf[0] = -1e30f; sf[2] = -1e30f; }
                        if (kc0 + 1 >= len) { sf[1] = -1e30f; sf[3] = -1e30f; }
                    }
                    ef[mg][2*half + 0] = exp2h2(sf[0], sf[1]);
                    ef[mg][2*half + 1] = exp2h2(sf[2], sf[3]);
                }
            }
            // --- PV + l for this chunk ---
            uint32_t vb[3][2];
            #pragma unroll
            for (int nd = 0; nd < 3; ++nd) {
                vb[nd][0] = Vt[(nd*8 + g)*VTP + kg*8 + t];
                vb[nd][1] = Vt[(nd*8 + g)*VTP + kg*8 + t + 4];
            }
            #pragma unroll
            for (int mg = 0; mg < 2; ++mg) {
                mma_f16(of[mg][0], ef[mg][0], ef[mg][1], ef[mg][2], ef[mg][3], vb[0][0], vb[0][1]);
                mma_f16(of[mg][1], ef[mg][0], ef[mg][1], ef[mg][2], ef[mg][3], vb[1][0], vb[1][1]);
                mma_f16(of2[mg],   ef[mg][0], ef[mg][1], ef[mg][2], ef[mg][3], vb[2][0], vb[2][1]);
            }
        }
    }

    // l lives in column 0 (lanes t==0); broadcast within each row quad
    #pragma unroll
    for (int mg = 0; mg < 2; ++mg) {
        const float l0 = __shfl_sync(0xffffffffu, of2[mg][0], lane & ~3);
        const float l1 = __shfl_sync(0xffffffffu, of2[mg][2], lane & ~3);
        const float inv0 = 1.0f / l0;
        const float inv1 = 1.0f / l1;
        const int r0 = qb + mg*16 + g, r1 = r0 + 8;
        #pragma unroll
        for (int nd = 0; nd < 2; ++nd) {
            const int ci = h*8 + nd*4 + t;
            att[(size_t)(b*NN + r0)*64 + ci] = packbf(of[mg][nd][0]*inv0, of[mg][nd][1]*inv0);
            att[(size_t)(b*NN + r1)*64 + ci] = packbf(of[mg][nd][2]*inv1, of[mg][nd][3]*inv1);
        }
    }
}

// ---------------- 4) pooled decoders: stage 1 (parallel column sums) ----------------
__global__ void colsum_kernel(const int* __restrict__ length) {
    const int b = blockIdx.x >> 3, seg = blockIdx.x & 7;
    const int d = threadIdx.x;
    const int len = length[b];
    const int n0 = seg * 128;
    const int n1 = min(n0 + 128, len);
    const float* p = g_eig + (size_t)b*NN*DD + d;
    float s = 0.f;
    for (int n = n0; n < n1; ++n) s += p[(size_t)n*DD];
    g_part[(b*8 + seg)*DD + d] = s;
}

// ---------------- 5) pooled decoders: stage 2 ----------------
__global__ void pooled_kernel(const int* __restrict__ length,
                              const float* __restrict__ Wsca, const float* __restrict__ bsca,
                              const float* __restrict__ Wwav, const float* __restrict__ bwav,
                              const float* __restrict__ Wscl, const float* __restrict__ bscl) {
    __shared__ float ssum[128];
    __shared__ float co[20];
    const int b = blockIdx.x, t = threadIdx.x;
    const int len = length[b];
    {
        const float* pp = g_part + b*8*DD + t;
        float s = 0.f;
        #pragma unroll
        for (int seg = 0; seg < 8; ++seg) s += pp[seg*DD];
        ssum[t] = s;
    }
    __syncthreads();
    if (t < 20) {
        const float* W; float bb;
        if (t < 8)        { W = Wsca + t*128;      bb = bsca[t]; }
        else if (t < 16)  { W = Wwav + (t-8)*128;  bb = bwav[t-8]; }
        else              { W = Wscl + (t-16)*128; bb = bscl[t-16]; }
        float a = 0.f;
        #pragma unroll 8
        for (int k = 0; k < 128; ++k) a += ssum[k] * W[k];
        const float lenf = (float)len;
        a = (a + lenf*bb) / (lenf + 1e-8f);
        co[t] = 1.0f / (1.0f + expf(-a));
    }
    __syncthreads();
    if (t == 0) {
        float s1 = 0.f, s2 = 0.f;
        for (int i = 0; i < 8; ++i) { s1 += co[i]; s2 += co[8+i]; }
        const float i1 = 1.0f/(s1 + 1e-8f), i2 = 1.0f/(s2 + 1e-8f);
        for (int i = 0; i < 8; ++i) {
            g_coe[b*20 + i]     = co[i]   * i1;
            g_coe[b*20 + 8 + i] = co[8+i] * i2;
        }
        for (int i = 0; i < 4; ++i) g_coe[b*20 + 16 + i] = co[16+i] * 2.0f;
    }
}

// ---------------- 6) Chebyshev bases + tight-frame output ----------------
__global__ void final_kernel(const float* __restrict__ eva, float* __restrict__ out) {
    const int idx = blockIdx.x*256 + threadIdx.x;
    if (idx >= ROWS) return;
    const int b = idx / NN;
    const float ev = eva[idx];
    const float* coe = g_coe + b*20;

    float y = ev - 1.0f;
    float te = 1.0f, to = y;
    float s = coe[0] * 0.5f * (1.0f - to);
    #pragma unroll
    for (int k = 1; k < 8; ++k) {
        te = 2.0f*y*to - te;
        to = 2.0f*y*te - to;
        s += coe[k] * 0.5f * (1.0f - to);
    }
    float w[4];
    #pragma unroll
    for (int j = 0; j < 4; ++j) {
        float f = ev * coe[16 + j];
        if (f > 2.0f) f = 0.0f;
        const float yj = f - 1.0f;
        float te2 = 1.0f, to2 = yj;
        float a = coe[8] * 0.5f * (1.0f - te2);
        #pragma unroll
        for (int k = 1; k < 8; ++k) {
            te2 = 2.0f*yj*to2 - te2;
            to2 = 2.0f*yj*te2 - to2;
            a += coe[8 + k] * 0.5f * (1.0f - te2);
        }
        w[j] = a;
    }
    const float nrm = sqrtf(s*s + w[0]*w[0] + w[1]*w[1] + w[2]*w[2] + w[3]*w[3]);
    const float inv = 1.0f / (nrm + 1e-8f);
    float* o = out + (size_t)idx * 5;
    o[0] = s*inv; o[1] = w[0]*inv; o[2] = w[1]*inv; o[3] = w[2]*inv; o[4] = w[3]*inv;
}

// ---------------- host launch ----------------
extern "C" void kernel_launch(void* const* d_in, const int* in_sizes, int n_in,
                              void* d_out, int out_size) {
    const float* eva    = (const float*)d_in[1];
    const int*   length = (const int*)  d_in[2];
    const float* eigW   = (const float*)d_in[3];
    const float* eigB   = (const float*)d_in[4];
    const float* ln1s   = (const float*)d_in[5];
    const float* ln1b   = (const float*)d_in[6];
    const float* ln2s   = (const float*)d_in[7];
    const float* ln2b   = (const float*)d_in[8];
    const float* qkvW   = (const float*)d_in[9];
    const float* qkvB   = (const float*)d_in[10];
    const float* outW   = (const float*)d_in[11];
    const float* outB   = (const float*)d_in[12];
    const float* f1W    = (const float*)d_in[13];
    const float* f1B    = (const float*)d_in[14];
    const float* f2W    = (const float*)d_in[15];
    const float* f2B    = (const float*)d_in[16];
    const float* dsW    = (const float*)d_in[17];
    const float* dsB    = (const float*)d_in[18];
    const float* dwW    = (const float*)d_in[19];
    const float* dwB    = (const float*)d_in[20];
    const float* dlW    = (const float*)d_in[21];
    const float* dlB    = (const float*)d_in[22];

    float *p_eig, *p_qkvbias;
    void *p_h1, *p_qkv4, *p_att4, *p_h2, *p_f14, *p_wqkv, *p_wout, *p_wf1, *p_wf2;
    cudaGetSymbolAddress((void**)&p_eig, g_eig);
    cudaGetSymbolAddress((void**)&p_qkvbias, g_qkvbias);
    cudaGetSymbolAddress(&p_h1,   g_h1);
    cudaGetSymbolAddress(&p_qkv4, g_qkv4);
    cudaGetSymbolAddress(&p_att4, g_att4);
    cudaGetSymbolAddress(&p_h2,   g_h2);
    cudaGetSymbolAddress(&p_f14,  g_f14);
    cudaGetSymbolAddress(&p_wqkv, g_wqkv4);
    cudaGetSymbolAddress(&p_wout, g_wout4);
    cudaGetSymbolAddress(&p_wf1,  g_wf14);
    cudaGetSymbolAddress(&p_wf2,  g_wf24);
    (void)in_sizes; (void)n_in; (void)out_size;

    const int ENC_SMEM = (128*132 + 4*132) * (int)sizeof(float);
    const int OLN_SMEM = (64*68 + 128*68) * (int)sizeof(uint32_t);
    cudaFuncSetAttribute(encode_kernel, cudaFuncAttributeMaxDynamicSharedMemorySize, ENC_SMEM);
    cudaFuncSetAttribute(gemm_oln,      cudaFuncAttributeMaxDynamicSharedMemorySize, OLN_SMEM);

    // 0) weights -> bf16 (q pre-scaled)
    wconv_kernel<<<64, 256>>>(qkvW, qkvB, outW, f1W, f2W);
    // 1) encode + LN1 -> g_eig (fp32), g_h1 (bf16)
    encode_kernel<<<ROWS/64, 128, ENC_SMEM>>>(eva, eigW, eigB, ln1s, ln1b);
    // 2) QKV -> g_qkv4 (q|k bf16, v f16)
    gemm_bb<3><<<dim3(6, ROWS/64), 128>>>((const __nv_bfloat16*)p_h1, (const __nv_bfloat16*)p_wqkv,
                                          p_qkvbias, nullptr, (uint32_t*)p_qkv4, nullptr, 3*DD);
    // 3) attention -> g_att4 (bf16)
    attn_kernel<<<dim3(NN/128, BB*HH), 128>>>((const uint32_t*)p_qkv4, (uint32_t*)p_att4, length);
    // 4) out proj + residual + LN2 -> g_eig (fp32), g_h2 (bf16)
    gemm_oln<<<ROWS/64, 128, OLN_SMEM>>>((const __nv_bfloat16*)p_att4, (const __nv_bfloat16*)p_wout,
                                         outB, p_eig, (uint32_t*)p_h2, ln2s, ln2b);
    // 5) FFN1 (gelu) -> g_f14 (bf16)
    gemm_bb<1><<<dim3(2, ROWS/64), 128>>>((const __nv_bfloat16*)p_h2, (const __nv_bfloat16*)p_wf1,
                                          f1B, nullptr, (uint32_t*)p_f14, nullptr, DD);
    // 6) FFN2 + residual -> g_eig (fp32)
    gemm_bb<2><<<dim3(2, ROWS/64), 128>>>((const __nv_bfloat16*)p_f14, (const __nv_bfloat16*)p_wf2,
                                          f2B, p_eig, nullptr, p_eig, DD);
    // 7) pooled decoders -> g_coe
    colsum_kernel<<<BB*8, 128>>>(length);
    pooled_kernel<<<BB, 128>>>(length, dsW, dsB, dwW, dwB, dlW, dlB);
    // 8) Chebyshev + normalize -> d_out
    final_kernel<<<(ROWS + 255)/256, 256>>>(eva, (float*)d_out);
}

// round 16
// speedup vs baseline: 1.0564x; 1.0128x over previous
#include <cuda_runtime.h>
#include <cuda_bf16.h>
#include <cuda_fp16.h>
#include <math.h>
#include <stdint.h>

#define BB 16
#define NN 1024
#define DD 128
#define HH 8
#define NUMN 8
#define NUMJ 4
#define ROWS (BB*NN)   /* 16384 */

// ---------------- scratch (device globals; no allocation) ----------------
__device__ float g_eig[ROWS*DD];          // fp32 residual stream
__device__ float g_part[BB*8*DD];         // pooled partial sums
__device__ float g_coe[BB*20];
__device__ float g_qkvbias[3*DD];         // q-part pre-scaled
__device__ uint4 g_h1[ROWS*DD/8];         // bf16 LN1 output
__device__ uint4 g_qkv4[ROWS*3*DD/8];     // q|k bf16, v f16 (q pre-scaled)
__device__ uint4 g_att4[ROWS*DD/8];       // bf16 attention output
__device__ uint4 g_h2[ROWS*DD/8];         // bf16 LN2 output
__device__ uint4 g_f14[ROWS*DD/8];        // bf16 ffn intermediate
__device__ uint4 g_wqkv4[3*DD*DD/8];      // bf16 weights
__device__ uint4 g_wout4[DD*DD/8];
__device__ uint4 g_wf14[DD*DD/8];
__device__ uint4 g_wf24[DD*DD/8];

#define QSCALE (0.25f * 1.4426950408889634f)   /* 1/sqrt(dh) * log2(e) */

__device__ __forceinline__ uint32_t packbf(float lo, float hi) {
    __nv_bfloat162 v = __floats2bfloat162_rn(lo, hi);
    return *reinterpret_cast<uint32_t*>(&v);
}
__device__ __forceinline__ void mma_bf16(float c[4],
                                         uint32_t a0, uint32_t a1, uint32_t a2, uint32_t a3,
                                         uint32_t b0, uint32_t b1) {
    asm("mma.sync.aligned.m16n8k16.row.col.f32.bf16.bf16.f32 "
        "{%0,%1,%2,%3},{%4,%5,%6,%7},{%8,%9},{%0,%1,%2,%3};"
        : "+f"(c[0]), "+f"(c[1]), "+f"(c[2]), "+f"(c[3])
        : "r"(a0), "r"(a1), "r"(a2), "r"(a3), "r"(b0), "r"(b1));
}
__device__ __forceinline__ void mma_f16(float c[4],
                                        uint32_t a0, uint32_t a1, uint32_t a2, uint32_t a3,
                                        uint32_t b0, uint32_t b1) {
    asm("mma.sync.aligned.m16n8k16.row.col.f32.f16.f16.f32 "
        "{%0,%1,%2,%3},{%4,%5,%6,%7},{%8,%9},{%0,%1,%2,%3};"
        : "+f"(c[0]), "+f"(c[1]), "+f"(c[2]), "+f"(c[3])
        : "r"(a0), "r"(a1), "r"(a2), "r"(a3), "r"(b0), "r"(b1));
}
__device__ __forceinline__ uint32_t exp2h2(float lo, float hi) {
    __half2 h = h2exp2(__floats2half2_rn(lo, hi));   // 1 MUFU per 2 values
    return *reinterpret_cast<uint32_t*>(&h);
}
__device__ __forceinline__ uint32_t packh(float lo, float hi) {
    __half2 h = __floats2half2_rn(lo, hi);
    return *reinterpret_cast<uint32_t*>(&h);
}

// ---------------- 0) one-time weight conversion to bf16 ----------------
__global__ void wconv_kernel(const float* __restrict__ qkvW, const float* __restrict__ qkvB,
                             const float* __restrict__ outW, const float* __restrict__ f1W,
                             const float* __restrict__ f2W) {
    const int stride = gridDim.x * blockDim.x;
    const int i0 = blockIdx.x * blockDim.x + threadIdx.x;
    __nv_bfloat16* wq = (__nv_bfloat16*)g_wqkv4;
    __nv_bfloat16* wo = (__nv_bfloat16*)g_wout4;
    __nv_bfloat16* w1 = (__nv_bfloat16*)g_wf14;
    __nv_bfloat16* w2 = (__nv_bfloat16*)g_wf24;
    for (int i = i0; i < 3*DD*DD; i += stride) {
        float v = qkvW[i];
        if (i < DD*DD) v *= QSCALE;           // fold Q scale into Wq
        wq[i] = __float2bfloat16(v);
    }
    for (int i = i0; i < DD*DD; i += stride) {
        wo[i] = __float2bfloat16(outW[i]);
        w1[i] = __float2bfloat16(f1W[i]);
        w2[i] = __float2bfloat16(f2W[i]);
    }
    if (i0 < 3*DD) g_qkvbias[i0] = qkvB[i0] * (i0 < DD ? QSCALE : 1.0f);
}

// ---------------- 1) sine encoding + projection + fused LN1 (4 rows/iter) ----------------
__global__ void encode_kernel(const float* __restrict__ eva,
                              const float* __restrict__ W,
                              const float* __restrict__ bias,
                              const float* __restrict__ lns,
                              const float* __restrict__ lnb) {
    extern __shared__ float sm[];
    float* Wsh  = sm;            // [128][132]
    float* eeig = sm + 128*132;  // [4][132]
    __shared__ float red1[4][4];
    __shared__ float red2[4][4];
    const int t = threadIdx.x;   // 128
    const int wid = t >> 5, lane = t & 31;

    for (int idx = t; idx < 128*129; idx += 128) {
        int d = idx / 129, i = idx % 129;
        Wsh[d*132 + i] = W[idx];
    }
    const float bs = bias[t];
    const float s1 = lns[t], b1 = lnb[t];
    const int f = t & 63, rr = t >> 6;
    const float divt = expf(-(float)(2*f) * (9.210340371976184f / 128.0f));
    const int row0 = blockIdx.x * 64;
    uint32_t* h1 = (uint32_t*)g_h1;
    __syncthreads();

    for (int r4 = 0; r4 < 64; r4 += 4) {
        #pragma unroll
        for (int j = 0; j < 2; ++j) {
            const int r = rr + 2*j;
            const float e = eva[row0 + r4 + r];
            float pe = e * 100.0f * divt;
            float s, c;
            sincosf(pe, &s, &c);
            eeig[r*132 + 1 + f]  = s;
            eeig[r*132 + 65 + f] = c;
            if (f == 0) eeig[r*132] = e;
        }
        __syncthreads();

        float acc[4] = {bs, bs, bs, bs};
        const float4* Wv = (const float4*)(Wsh + t*132);
        const float4* E0 = (const float4*)(eeig);
        const float4* E1 = (const float4*)(eeig + 132);
        const float4* E2 = (const float4*)(eeig + 264);
        const float4* E3 = (const float4*)(eeig + 396);
        #pragma unroll 4
        for (int i4 = 0; i4 < 32; ++i4) {
            float4 w = Wv[i4];
            float4 e0 = E0[i4], e1 = E1[i4], e2 = E2[i4], e3 = E3[i4];
            acc[0] += w.x*e0.x + w.y*e0.y + w.z*e0.z + w.w*e0.w;
            acc[1] += w.x*e1.x + w.y*e1.y + w.z*e1.z + w.w*e1.w;
            acc[2] += w.x*e2.x + w.y*e2.y + w.z*e2.z + w.w*e2.w;
            acc[3] += w.x*e3.x + w.y*e3.y + w.z*e3.z + w.w*e3.w;
        }
        const float wlast = Wsh[t*132 + 128];
        #pragma unroll
        for (int r = 0; r < 4; ++r) acc[r] += wlast * eeig[r*132 + 128];

        // store fp32 + LN over 4 rows
        #pragma unroll
        for (int r = 0; r < 4; ++r) {
            g_eig[(size_t)(row0 + r4 + r)*DD + t] = acc[r];
            float x = acc[r];
            #pragma unroll
            for (int o = 16; o; o >>= 1) x += __shfl_xor_sync(0xffffffffu, x, o);
            if (lane == 0) red1[r][wid] = x;
        }
        __syncthreads();
        float dd[4];
        #pragma unroll
        for (int r = 0; r < 4; ++r) {
            const float mean = (red1[r][0]+red1[r][1]+red1[r][2]+red1[r][3]) * (1.0f/128.0f);
            dd[r] = acc[r] - mean;
            float q = dd[r] * dd[r];
            #pragma unroll
            for (int o = 16; o; o >>= 1) q += __shfl_xor_sync(0xffffffffu, q, o);
            if (lane == 0) red2[r][wid] = q;
        }
        __syncthreads();
        #pragma unroll
        for (int r = 0; r < 4; ++r) {
            const float var = (red2[r][0]+red2[r][1]+red2[r][2]+red2[r][3]) * (1.0f/128.0f);
            const float h = dd[r] * rsqrtf(var + 1e-5f) * s1 + b1;
            const float hh = __shfl_down_sync(0xffffffffu, h, 1);
            if (!(t & 1)) h1[(row0 + r4 + r)*64 + (t >> 1)] = packbf(h, hh);
        }
        __syncthreads();
    }
}

// ---------------- 2) bf16 GEMM, copy-only staging ----------------
// EPI 0: bf16 out; 1: gelu + bf16 out; 2: residual + fp32 out;
// EPI 3: qkv -> bf16 out for q|k columns, f16 out for v columns (n0 >= 256)
template <int EPI>
__global__ void __launch_bounds__(128) gemm_bb(const __nv_bfloat16* __restrict__ A,
                                               const __nv_bfloat16* __restrict__ W,
                                               const float* __restrict__ bias,
                                               const float* __restrict__ res,
                                               uint32_t* __restrict__ Cb,
                                               float* __restrict__ Cf,
                                               int Nout) {
    __shared__ __align__(16) uint32_t As[64*68];
    __shared__ __align__(16) uint32_t Ws[64*68];
    const int tid  = threadIdx.x;          // 128
    const int m0   = blockIdx.y * 64;
    const int n0   = blockIdx.x * 64;
    const int warp = tid >> 5, lane = tid & 31;
    const int g = lane >> 2, t = lane & 3;
    const int wm = (warp >> 1) * 32, wn = (warp & 1) * 32;

    {
        const int r = tid >> 1, j0 = (tid & 1) * 8;
        const uint4* Ag = (const uint4*)(A + (size_t)(m0 + r) * 128) + j0;
        const uint4* Wg = (const uint4*)(W + (size_t)(n0 + r) * 128) + j0;
        uint4* Ad = (uint4*)(As + r*68) + j0;
        uint4* Wd = (uint4*)(Ws + r*68) + j0;
        #pragma unroll
        for (int j = 0; j < 8; ++j) { Ad[j] = Ag[j]; Wd[j] = Wg[j]; }
    }
    __syncthreads();

    float acc[2][4][4] = {};
    #pragma unroll
    for (int k = 0; k < 8; ++k) {
        const int k0 = k * 8;
        uint32_t af[2][4];
        #pragma unroll
        for (int mg = 0; mg < 2; ++mg) {
            const uint32_t* ap = As + (wm + mg*16 + g) * 68 + k0;
            af[mg][0] = ap[t];
            af[mg][1] = ap[8*68 + t];
            af[mg][2] = ap[t + 4];
            af[mg][3] = ap[8*68 + t + 4];
        }
        #pragma unroll
        for (int ng = 0; ng < 4; ++ng) {
            const uint32_t* wp = Ws + (wn + ng*8 + g) * 68 + k0;
            const uint32_t b0 = wp[t];
            const uint32_t b1 = wp[t + 4];
            mma_bf16(acc[0][ng], af[0][0], af[0][1], af[0][2], af[0][3], b0, b1);
            mma_bf16(acc[1][ng], af[1][0], af[1][1], af[1][2], af[1][3], b0, b1);
        }
    }

    const bool vf16 = (EPI == 3) && (n0 >= 256);   // V block -> f16 packing
    #pragma unroll
    for (int mg = 0; mg < 2; ++mg) {
        const int row0 = m0 + wm + mg*16 + g;
        const int row1 = row0 + 8;
        #pragma unroll
        for (int ng = 0; ng < 4; ++ng) {
            const int col = n0 + wn + ng*8 + 2*t;
            float2 b2 = *(const float2*)&bias[col];
            float2 v0 = make_float2(acc[mg][ng][0] + b2.x, acc[mg][ng][1] + b2.y);
            float2 v1 = make_float2(acc[mg][ng][2] + b2.x, acc[mg][ng][3] + b2.y);
            if (EPI == 1) {
                v0.x = 0.5f*v0.x*(1.0f + erff(v0.x*0.7071067811865475f));
                v0.y = 0.5f*v0.y*(1.0f + erff(v0.y*0.7071067811865475f));
                v1.x = 0.5f*v1.x*(1.0f + erff(v1.x*0.7071067811865475f));
                v1.y = 0.5f*v1.y*(1.0f + erff(v1.y*0.7071067811865475f));
            }
            if (EPI == 2) {
                float2 r0 = *(const float2*)&res[(size_t)row0*Nout + col];
                float2 r1 = *(const float2*)&res[(size_t)row1*Nout + col];
                v0.x += r0.x; v0.y += r0.y;
                v1.x += r1.x; v1.y += r1.y;
                *(float2*)&Cf[(size_t)row0*Nout + col] = v0;
                *(float2*)&Cf[(size_t)row1*Nout + col] = v1;
            } else {
                const int cb = (n0 + wn + ng*8) >> 1;
                uint32_t p0, p1;
                if (vf16) { p0 = packh(v0.x, v0.y);  p1 = packh(v1.x, v1.y); }
                else      { p0 = packbf(v0.x, v0.y); p1 = packbf(v1.x, v1.y); }
                Cb[(size_t)row0*(Nout >> 1) + cb + t] = p0;
                Cb[(size_t)row1*(Nout >> 1) + cb + t] = p1;
            }
        }
    }
}

// ---------------- 2b) out-proj GEMM + residual + fused LN2 ----------------
__global__ void __launch_bounds__(128) gemm_oln(const __nv_bfloat16* __restrict__ A,
                                                const __nv_bfloat16* __restrict__ W,
                                                const float* __restrict__ bias,
                                                float* __restrict__ eig,
                                                uint32_t* __restrict__ h2,
                                                const float* __restrict__ lns,
                                                const float* __restrict__ lnb) {
    extern __shared__ __align__(16) uint32_t smu[];
    uint32_t* As = smu;              // 64*68
    uint32_t* Ws = smu + 64*68;      // 128*68
    float* Hs = (float*)smu;         // 64*132 fp32 (reused after mma)
    const int tid = threadIdx.x;     // 128
    const int m0 = blockIdx.x * 64;
    const int warp = tid >> 5, lane = tid & 31;
    const int g = lane >> 2, t = lane & 3;
    const int wm = (warp >> 1) * 32, wn = (warp & 1) * 64;

    {
        const int r = tid >> 1, j0 = (tid & 1) * 8;
        const uint4* Ag = (const uint4*)(A + (size_t)(m0 + r) * 128) + j0;
        uint4* Ad = (uint4*)(As + r*68) + j0;
        #pragma unroll
        for (int j = 0; j < 8; ++j) Ad[j] = Ag[j];
        const uint4* Wg = (const uint4*)(W + (size_t)tid * 128);
        uint4* Wd = (uint4*)(Ws + tid*68);
        #pragma unroll
        for (int j = 0; j < 16; ++j) Wd[j] = Wg[j];
    }
    __syncthreads();

    float acc[2][8][4] = {};
    #pragma unroll
    for (int k = 0; k < 8; ++k) {
        const int k0 = k * 8;
        uint32_t af[2][4];
        #pragma unroll
        for (int mg = 0; mg < 2; ++mg) {
            const uint32_t* ap = As + (wm + mg*16 + g) * 68 + k0;
            af[mg][0] = ap[t];
            af[mg][1] = ap[8*68 + t];
            af[mg][2] = ap[t + 4];
            af[mg][3] = ap[8*68 + t + 4];
        }
        #pragma unroll
        for (int ng = 0; ng < 8; ++ng) {
            const uint32_t* wp = Ws + (wn + ng*8 + g) * 68 + k0;
            const uint32_t b0 = wp[t];
            const uint32_t b1 = wp[t + 4];
            mma_bf16(acc[0][ng], af[0][0], af[0][1], af[0][2], af[0][3], b0, b1);
            mma_bf16(acc[1][ng], af[1][0], af[1][1], af[1][2], af[1][3], b0, b1);
        }
    }
    __syncthreads();   // all smem reads done; Hs may now overwrite

    #pragma unroll
    for (int mg = 0; mg < 2; ++mg) {
        const int rl0 = wm + mg*16 + g, rl1 = rl0 + 8;
        #pragma unroll
        for (int ng = 0; ng < 8; ++ng) {
            const int col = wn + ng*8 + 2*t;
            float2 b2 = *(const float2*)&bias[col];
            float2 r0 = *(const float2*)&eig[(size_t)(m0 + rl0)*DD + col];
            float2 r1 = *(const float2*)&eig[(size_t)(m0 + rl1)*DD + col];
            float2 v0 = make_float2(acc[mg][ng][0] + b2.x + r0.x, acc[mg][ng][1] + b2.y + r0.y);
            float2 v1 = make_float2(acc[mg][ng][2] + b2.x + r1.x, acc[mg][ng][3] + b2.y + r1.y);
            *(float2*)&eig[(size_t)(m0 + rl0)*DD + col] = v0;
            *(float2*)&eig[(size_t)(m0 + rl1)*DD + col] = v1;
            *(float2*)&Hs[rl0*132 + col] = v0;
            *(float2*)&Hs[rl1*132 + col] = v1;
        }
    }
    __syncthreads();

    // LN2 over the 64 in-smem rows: warp w handles rows [16w, 16w+16)
    const float4 ls = *(const float4*)&lns[4*lane];
    const float4 lb = *(const float4*)&lnb[4*lane];
    for (int rl = warp*16; rl < warp*16 + 16; ++rl) {
        float4 v = *(const float4*)&Hs[rl*132 + 4*lane];
        float s = v.x + v.y + v.z + v.w;
        float q = v.x*v.x + v.y*v.y + v.z*v.z + v.w*v.w;
        #pragma unroll
        for (int o = 16; o; o >>= 1) {
            s += __shfl_xor_sync(0xffffffffu, s, o);
            q += __shfl_xor_sync(0xffffffffu, q, o);
        }
        const float mean = s * (1.0f/128.0f);
        const float var  = q * (1.0f/128.0f) - mean*mean;
        const float inv  = rsqrtf(var + 1e-5f);
        const float h0 = (v.x - mean)*inv*ls.x + lb.x;
        const float h1v = (v.y - mean)*inv*ls.y + lb.y;
        const float h2v = (v.z - mean)*inv*ls.z + lb.z;
        const float h3 = (v.w - mean)*inv*ls.w + lb.w;
        uint2 o2;
        o2.x = packbf(h0, h1v);
        o2.y = packbf(h2v, h3);
        *(uint2*)&h2[(size_t)(m0 + rl)*64 + 2*lane] = o2;
    }
}

// ---------------- 3) flash attention: 2 q-blocks/CTA, pipelined staging ----------------
// Warp owns 64 queries (4 row-groups); each staged K/V tile feeds 2x the mma/exp work.
#define KSP 12
#define VTP 36

__global__ void __launch_bounds__(128, 4) attn_kernel(const uint32_t* __restrict__ qkv,
                                                      uint32_t* __restrict__ att,
                                                      const int* __restrict__ length) {
    const int bh   = blockIdx.y;
    const int b    = bh >> 3, h = bh & 7;
    const int warp = threadIdx.x >> 5;
    const int lane = threadIdx.x & 31;
    const int g    = lane >> 2, t = lane & 3;
    const int qb   = blockIdx.x * 256 + warp * 64;   // 64 queries per warp
    const int len  = length[b];

    __shared__ __align__(16) uint32_t Ks[64 * KSP];
    __shared__ __align__(16) uint32_t Vt[24 * VTP];   // rows 0..15 V(f16), 16 ones, 17..23 zeros

    const uint32_t* base = qkv + (size_t)b * NN * 192;

    // ones/zeros rows for the l-sum column (constant across tiles)
    for (int i = threadIdx.x; i < 8*VTP; i += 128)
        Vt[16*VTP + i] = (i < VTP) ? 0x3C003C00u : 0u;

    uint32_t qf[4][4];
    #pragma unroll
    for (int mg = 0; mg < 4; ++mg) {
        const uint32_t* q0 = base + (size_t)(qb + mg*16 + g)*192 + h*8;
        const uint32_t* q1 = q0 + 8*192;
        qf[mg][0] = q0[t];
        qf[mg][1] = q1[t];
        qf[mg][2] = q0[t + 4];
        qf[mg][3] = q1[t + 4];
    }

    // staging addresses (loop-invariant)
    const int skey = threadIdx.x >> 1, sc4 = (threadIdx.x & 1) * 4;
    const uint32_t* kptr = base + (size_t)skey*192 + 64 + h*8 + sc4;
    const int skp = threadIdx.x & 31, sdg = (threadIdx.x >> 5) * 4;
    const uint32_t* vptr = base + (size_t)(2*skp)*192 + 128 + h*8 + (sdg >> 1);

    float of[4][2][4] = {};
    float of2[4][4] = {};     // l accumulators via ones-column mma

    // prologue: load tile 0
    uint4 kreg = *(const uint4*)kptr;
    uint2 areg = *(const uint2*)vptr;
    uint2 creg = *(const uint2*)(vptr + 192);

    for (int k0 = 0; k0 < len; k0 += 64) {
        __syncthreads();   // prev tile's smem fully consumed
        // store held registers to smem
        *(uint4*)(Ks + skey*KSP + sc4) = kreg;
        Vt[(sdg+0)*VTP + skp] = __byte_perm(areg.x, creg.x, 0x5410);
        Vt[(sdg+1)*VTP + skp] = __byte_perm(areg.x, creg.x, 0x7632);
        Vt[(sdg+2)*VTP + skp] = __byte_perm(areg.y, creg.y, 0x5410);
        Vt[(sdg+3)*VTP + skp] = __byte_perm(areg.y, creg.y, 0x7632);
        // prefetch next tile (latency overlaps this tile's compute)
        if (k0 + 64 < len) {
            const size_t off = (size_t)(k0 + 64) * 192;
            kreg = *(const uint4*)(kptr + off);
            areg = *(const uint2*)(vptr + off);
            creg = *(const uint2*)(vptr + off + 192);
        }
        __syncthreads();

        const bool tail = (k0 + 64 > len);
        #pragma unroll
        for (int kg = 0; kg < 4; ++kg) {
            // --- QK + exp for the two 8-key groups of this chunk, all 4 row-groups ---
            uint32_t ef[4][4];
            #pragma unroll
            for (int half = 0; half < 2; ++half) {
                const int ng = 2*kg + half;
                const int key = ng*8 + g;
                const uint32_t b0 = Ks[key*KSP + t];
                const uint32_t b1 = Ks[key*KSP + t + 4];
                #pragma unroll
                for (int mg = 0; mg < 4; ++mg) {
                    float sf[4] = {0.f, 0.f, 0.f, 0.f};
                    mma_bf16(sf, qf[mg][0], qf[mg][1], qf[mg][2], qf[mg][3], b0, b1);
                    if (tail) {        // uniform branch; -1e30 -> f16 -inf -> exp 0
                        const int kc0 = k0 + ng*8 + 2*t;
                        if (kc0 >= len)     { sf[0] = -1e30f; sf[2] = -1e30f; }
                        if (kc0 + 1 >= len) { sf[1] = -1e30f; sf[3] = -1e30f; }
                    }
                    ef[mg][2*half + 0] = exp2h2(sf[0], sf[1]);
                    ef[mg][2*half + 1] = exp2h2(sf[2], sf[3]);
                }
            }
            // --- PV + l for this chunk ---
            uint32_t vb[3][2];
            #pragma unroll
            for (int nd = 0; nd < 3; ++nd) {
                vb[nd][0] = Vt[(nd*8 + g)*VTP + kg*8 + t];
                vb[nd][1] = Vt[(nd*8 + g)*VTP + kg*8 + t + 4];
            }
            #pragma unroll
            for (int mg = 0; mg < 4; ++mg) {
                mma_f16(of[mg][0], ef[mg][0], ef[mg][1], ef[mg][2], ef[mg][3], vb[0][0], vb[0][1]);
                mma_f16(of[mg][1], ef[mg][0], ef[mg][1], ef[mg][2], ef[mg][3], vb[1][0], vb[1][1]);
                mma_f16(of2[mg],   ef[mg][0], ef[mg][1], ef[mg][2], ef[mg][3], vb[2][0], vb[2][1]);
            }
        }
    }

    // l lives in column 0 (lanes t==0); broadcast within each row quad
    #pragma unroll
    for (int mg = 0; mg < 4; ++mg) {
        const float l0 = __shfl_sync(0xffffffffu, of2[mg][0], lane & ~3);
        const float l1 = __shfl_sync(0xffffffffu, of2[mg][2], lane & ~3);
        const float inv0 = 1.0f / l0;
        const float inv1 = 1.0f / l1;
        const int r0 = qb + mg*16 + g, r1 = r0 + 8;
        #pragma unroll
        for (int nd = 0; nd < 2; ++nd) {
            const int ci = h*8 + nd*4 + t;
            att[(size_t)(b*NN + r0)*64 + ci] = packbf(of[mg][nd][0]*inv0, of[mg][nd][1]*inv0);
            att[(size_t)(b*NN + r1)*64 + ci] = packbf(of[mg][nd][2]*inv1, of[mg][nd][3]*inv1);
        }
    }
}

// ---------------- 4) pooled decoders: stage 1 (parallel column sums) ----------------
__global__ void colsum_kernel(const int* __restrict__ length) {
    const int b = blockIdx.x >> 3, seg = blockIdx.x & 7;
    const int d = threadIdx.x;
    const int len = length[b];
    const int n0 = seg * 128;
    const int n1 = min(n0 + 128, len);
    const float* p = g_eig + (size_t)b*NN*DD + d;
    float s = 0.f;
    for (int n = n0; n < n1; ++n) s += p[(size_t)n*DD];
    g_part[(b*8 + seg)*DD + d] = s;
}

// ---------------- 5) pooled decoders: stage 2 ----------------
__global__ void pooled_kernel(const int* __restrict__ length,
                              const float* __restrict__ Wsca, const float* __restrict__ bsca,
                              const float* __restrict__ Wwav, const float* __restrict__ bwav,
                              const float* __restrict__ Wscl, const float* __restrict__ bscl) {
    __shared__ float ssum[128];
    __shared__ float co[20];
    const int b = blockIdx.x, t = threadIdx.x;
    const int len = length[b];
    {
        const float* pp = g_part + b*8*DD + t;
        float s = 0.f;
        #pragma unroll
        for (int seg = 0; seg < 8; ++seg) s += pp[seg*DD];
        ssum[t] = s;
    }
    __syncthreads();
    if (t < 20) {
        const float* W; float bb;
        if (t < 8)        { W = Wsca + t*128;      bb = bsca[t]; }
        else if (t < 16)  { W = Wwav + (t-8)*128;  bb = bwav[t-8]; }
        else              { W = Wscl + (t-16)*128; bb = bscl[t-16]; }
        float a = 0.f;
        #pragma unroll 8
        for (int k = 0; k < 128; ++k) a += ssum[k] * W[k];
        const float lenf = (float)len;
        a = (a + lenf*bb) / (lenf + 1e-8f);
        co[t] = 1.0f / (1.0f + expf(-a));
    }
    __syncthreads();
    if (t == 0) {
        float s1 = 0.f, s2 = 0.f;
        for (int i = 0; i < 8; ++i) { s1 += co[i]; s2 += co[8+i]; }
        const float i1 = 1.0f/(s1 + 1e-8f), i2 = 1.0f/(s2 + 1e-8f);
        for (int i = 0; i < 8; ++i) {
            g_coe[b*20 + i]     = co[i]   * i1;
            g_coe[b*20 + 8 + i] = co[8+i] * i2;
        }
        for (int i = 0; i < 4; ++i) g_coe[b*20 + 16 + i] = co[16+i] * 2.0f;
    }
}

// ---------------- 6) Chebyshev bases + tight-frame output ----------------
__global__ void final_kernel(const float* __restrict__ eva, float* __restrict__ out) {
    const int idx = blockIdx.x*256 + threadIdx.x;
    if (idx >= ROWS) return;
    const int b = idx / NN;
    const float ev = eva[idx];
    const float* coe = g_coe + b*20;

    float y = ev - 1.0f;
    float te = 1.0f, to = y;
    float s = coe[0] * 0.5f * (1.0f - to);
    #pragma unroll
    for (int k = 1; k < 8; ++k) {
        te = 2.0f*y*to - te;
        to = 2.0f*y*te - to;
        s += coe[k] * 0.5f * (1.0f - to);
    }
    float w[4];
    #pragma unroll
    for (int j = 0; j < 4; ++j) {
        float f = ev * coe[16 + j];
        if (f > 2.0f) f = 0.0f;
        const float yj = f - 1.0f;
        float te2 = 1.0f, to2 = yj;
        float a = coe[8] * 0.5f * (1.0f - te2);
        #pragma unroll
        for (int k = 1; k < 8; ++k) {
            te2 = 2.0f*yj*to2 - te2;
            to2 = 2.0f*yj*te2 - to2;
            a += coe[8 + k] * 0.5f * (1.0f - te2);
        }
        w[j] = a;
    }
    const float nrm = sqrtf(s*s + w[0]*w[0] + w[1]*w[1] + w[2]*w[2] + w[3]*w[3]);
    const float inv = 1.0f / (nrm + 1e-8f);
    float* o = out + (size_t)idx * 5;
    o[0] = s*inv; o[1] = w[0]*inv; o[2] = w[1]*inv; o[3] = w[2]*inv; o[4] = w[3]*inv;
}

// ---------------- host launch ----------------
extern "C" void kernel_launch(void* const* d_in, const int* in_sizes, int n_in,
                              void* d_out, int out_size) {
    const float* eva    = (const float*)d_in[1];
    const int*   length = (const int*)  d_in[2];
    const float* eigW   = (const float*)d_in[3];
    const float* eigB   = (const float*)d_in[4];
    const float* ln1s   = (const float*)d_in[5];
    const float* ln1b   = (const float*)d_in[6];
    const float* ln2s   = (const float*)d_in[7];
    const float* ln2b   = (const float*)d_in[8];
    const float* qkvW   = (const float*)d_in[9];
    const float* qkvB   = (const float*)d_in[10];
    const float* outW   = (const float*)d_in[11];
    const float* outB   = (const float*)d_in[12];
    const float* f1W    = (const float*)d_in[13];
    const float* f1B    = (const float*)d_in[14];
    const float* f2W    = (const float*)d_in[15];
    const float* f2B    = (const float*)d_in[16];
    const float* dsW    = (const float*)d_in[17];
    const float* dsB    = (const float*)d_in[18];
    const float* dwW    = (const float*)d_in[19];
    const float* dwB    = (const float*)d_in[20];
    const float* dlW    = (const float*)d_in[21];
    const float* dlB    = (const float*)d_in[22];

    float *p_eig, *p_qkvbias;
    void *p_h1, *p_qkv4, *p_att4, *p_h2, *p_f14, *p_wqkv, *p_wout, *p_wf1, *p_wf2;
    cudaGetSymbolAddress((void**)&p_eig, g_eig);
    cudaGetSymbolAddress((void**)&p_qkvbias, g_qkvbias);
    cudaGetSymbolAddress(&p_h1,   g_h1);
    cudaGetSymbolAddress(&p_qkv4, g_qkv4);
    cudaGetSymbolAddress(&p_att4, g_att4);
    cudaGetSymbolAddress(&p_h2,   g_h2);
    cudaGetSymbolAddress(&p_f14,  g_f14);
    cudaGetSymbolAddress(&p_wqkv, g_wqkv4);
    cudaGetSymbolAddress(&p_wout, g_wout4);
    cudaGetSymbolAddress(&p_wf1,  g_wf14);
    cudaGetSymbolAddress(&p_wf2,  g_wf24);
    (void)in_sizes; (void)n_in; (void)out_size;

    const int ENC_SMEM = (128*132 + 4*132) * (int)sizeof(float);
    const int OLN_SMEM = (64*68 + 128*68) * (int)sizeof(uint32_t);
    cudaFuncSetAttribute(encode_kernel, cudaFuncAttributeMaxDynamicSharedMemorySize, ENC_SMEM);
    cudaFuncSetAttribute(gemm_oln,      cudaFuncAttributeMaxDynamicSharedMemorySize, OLN_SMEM);

    // 0) weights -> bf16 (q pre-scaled)
    wconv_kernel<<<64, 256>>>(qkvW, qkvB, outW, f1W, f2W);
    // 1) encode + LN1 -> g_eig (fp32), g_h1 (bf16)
    encode_kernel<<<ROWS/64, 128, ENC_SMEM>>>(eva, eigW, eigB, ln1s, ln1b);
    // 2) QKV -> g_qkv4 (q|k bf16, v f16)
    gemm_bb<3><<<dim3(6, ROWS/64), 128>>>((const __nv_bfloat16*)p_h1, (const __nv_bfloat16*)p_wqkv,
                                          p_qkvbias, nullptr, (uint32_t*)p_qkv4, nullptr, 3*DD);
    // 3) attention -> g_att4 (bf16)
    attn_kernel<<<dim3(NN/256, BB*HH), 128>>>((const uint32_t*)p_qkv4, (uint32_t*)p_att4, length);
    // 4) out proj + residual + LN2 -> g_eig (fp32), g_h2 (bf16)
    gemm_oln<<<ROWS/64, 128, OLN_SMEM>>>((const __nv_bfloat16*)p_att4, (const __nv_bfloat16*)p_wout,
                                         outB, p_eig, (uint32_t*)p_h2, ln2s, ln2b);
    // 5) FFN1 (gelu) -> g_f14 (bf16)
    gemm_bb<1><<<dim3(2, ROWS/64), 128>>>((const __nv_bfloat16*)p_h2, (const __nv_bfloat16*)p_wf1,
                                          f1B, nullptr, (uint32_t*)p_f14, nullptr, DD);
    // 6) FFN2 + residual -> g_eig (fp32)
    gemm_bb<2><<<dim3(2, ROWS/64), 128>>>((const __nv_bfloat16*)p_f14, (const __nv_bfloat16*)p_wf2,
                                          f2B, p_eig, nullptr, p_eig, DD);
    // 7) pooled decoders -> g_coe
    colsum_kernel<<<BB*8, 128>>>(length);
    pooled_kernel<<<BB, 128>>>(length, dsW, dsB, dwW, dwB, dlW, dlB);
    // 8) Chebyshev + normalize -> d_out
    final_kernel<<<(ROWS + 255)/256, 256>>>(eva, (float*)d_out);
}